// round 2
// baseline (speedup 1.0000x reference)
#include <cuda_runtime.h>
#include <math.h>

#define BATCH 2
#define NSEQ 1536
#define DIMX 1536
#define HEADS 8
#define DK 64
#define HD 512          // HEADS*DK
#define BN 3072         // BATCH*NSEQ
#define NPOS 3071       // 2N-1
#define NRPFK 192

// ---------------- scratch (static device arrays; no allocation) ----------------
__device__ __align__(16) float g_qc[16 * 1536 * 64];   // q*scale + rel_content_bias, [b*h][i][d]
__device__ __align__(16) float g_qr[16 * 1536 * 64];   // q*scale + rel_pos_bias
__device__ __align__(16) float g_k [16 * 1536 * 64];
__device__ __align__(16) float g_v [16 * 1536 * 64];
__device__ __align__(16) float g_relk[3071 * 512];     // pos_embed @ Wrel, [j2][h*64+d]
__device__ __align__(16) float g_ao[3072 * 512];       // attention out, [b*n][h*64+d]

// ---------------- fused QKV projection GEMM (128x128 tile, 8x8/thread) ----------------
__global__ __launch_bounds__(256) void qkv_gemm(
    const float* __restrict__ x, const float* __restrict__ Wq,
    const float* __restrict__ Wk, const float* __restrict__ Wv,
    const float* __restrict__ rcb, const float* __restrict__ rpb)
{
    const int z = blockIdx.z;                       // 0=q, 1=k, 2=v
    const float* Bm = (z == 0) ? Wq : (z == 1) ? Wk : Wv;
    const int m0 = blockIdx.y * 128;
    const int n0 = blockIdx.x * 128;

    __shared__ float As[8][128];
    __shared__ float Bs[8][128];

    const int tid  = threadIdx.x;
    const int arow = tid >> 1, akq = (tid & 1) * 4;
    const int bkk  = tid >> 5, bcol = (tid & 31) * 4;
    const int tr   = tid >> 4, tc = tid & 15;

    float acc[8][8];
    #pragma unroll
    for (int i = 0; i < 8; i++)
        #pragma unroll
        for (int j = 0; j < 8; j++) acc[i][j] = 0.f;

    for (int k0 = 0; k0 < DIMX; k0 += 8) {
        float4 av = *(const float4*)&x [(m0 + arow) * DIMX + k0 + akq];
        float4 bv = *(const float4*)&Bm[(k0 + bkk) * HD + n0 + bcol];
        __syncthreads();
        As[akq + 0][arow] = av.x; As[akq + 1][arow] = av.y;
        As[akq + 2][arow] = av.z; As[akq + 3][arow] = av.w;
        *(float4*)&Bs[bkk][bcol] = bv;
        __syncthreads();
        #pragma unroll
        for (int kk = 0; kk < 8; kk++) {
            float4 a0 = *(const float4*)&As[kk][tr * 8];
            float4 a1 = *(const float4*)&As[kk][tr * 8 + 4];
            float4 b0 = *(const float4*)&Bs[kk][tc * 8];
            float4 b1 = *(const float4*)&Bs[kk][tc * 8 + 4];
            float a[8] = {a0.x, a0.y, a0.z, a0.w, a1.x, a1.y, a1.z, a1.w};
            float b[8] = {b0.x, b0.y, b0.z, b0.w, b1.x, b1.y, b1.z, b1.w};
            #pragma unroll
            for (int i = 0; i < 8; i++)
                #pragma unroll
                for (int j = 0; j < 8; j++) acc[i][j] += a[i] * b[j];
        }
    }

    // epilogue: relayout to [b*H+h][i][d]; q gets scale + biases (two outputs)
    #pragma unroll
    for (int i = 0; i < 8; i++) {
        int gm = m0 + tr * 8 + i;
        int bb = gm / NSEQ;
        int ii = gm - bb * NSEQ;
        #pragma unroll
        for (int j = 0; j < 8; j++) {
            int gn = n0 + tc * 8 + j;
            int hh = gn >> 6, dd = gn & 63;
            int idx = ((bb * HEADS + hh) * NSEQ + ii) * DK + dd;
            float v = acc[i][j];
            if (z == 0) {
                g_qc[idx] = v * 0.125f + rcb[gn];
                g_qr[idx] = v * 0.125f + rpb[gn];
            } else if (z == 1) {
                g_k[idx] = v;
            } else {
                g_v[idx] = v;
            }
        }
    }
}

// ---------------- generic SGEMM with optional bias (row guards on M) ----------------
__global__ __launch_bounds__(256) void sgemm_bias(
    const float* __restrict__ A, const float* __restrict__ Bm, float* __restrict__ C,
    int M, int N, int K, const float* __restrict__ bias)
{
    const int m0 = blockIdx.y * 128;
    const int n0 = blockIdx.x * 128;

    __shared__ float As[8][128];
    __shared__ float Bs[8][128];

    const int tid  = threadIdx.x;
    const int arow = tid >> 1, akq = (tid & 1) * 4;
    const int bkk  = tid >> 5, bcol = (tid & 31) * 4;
    const int tr   = tid >> 4, tc = tid & 15;

    float acc[8][8];
    #pragma unroll
    for (int i = 0; i < 8; i++)
        #pragma unroll
        for (int j = 0; j < 8; j++) acc[i][j] = 0.f;

    for (int k0 = 0; k0 < K; k0 += 8) {
        float4 av = make_float4(0.f, 0.f, 0.f, 0.f);
        if (m0 + arow < M) av = *(const float4*)&A[(m0 + arow) * K + k0 + akq];
        float4 bv = *(const float4*)&Bm[(k0 + bkk) * N + n0 + bcol];
        __syncthreads();
        As[akq + 0][arow] = av.x; As[akq + 1][arow] = av.y;
        As[akq + 2][arow] = av.z; As[akq + 3][arow] = av.w;
        *(float4*)&Bs[bkk][bcol] = bv;
        __syncthreads();
        #pragma unroll
        for (int kk = 0; kk < 8; kk++) {
            float4 a0 = *(const float4*)&As[kk][tr * 8];
            float4 a1 = *(const float4*)&As[kk][tr * 8 + 4];
            float4 b0 = *(const float4*)&Bs[kk][tc * 8];
            float4 b1 = *(const float4*)&Bs[kk][tc * 8 + 4];
            float a[8] = {a0.x, a0.y, a0.z, a0.w, a1.x, a1.y, a1.z, a1.w};
            float b[8] = {b0.x, b0.y, b0.z, b0.w, b1.x, b1.y, b1.z, b1.w};
            #pragma unroll
            for (int i = 0; i < 8; i++)
                #pragma unroll
                for (int j = 0; j < 8; j++) acc[i][j] += a[i] * b[j];
        }
    }

    #pragma unroll
    for (int i = 0; i < 8; i++) {
        int gm = m0 + tr * 8 + i;
        if (gm >= M) continue;
        #pragma unroll
        for (int j = 0; j < 8; j++) {
            int gn = n0 + tc * 8 + j;
            float v = acc[i][j];
            if (bias) v += bias[gn];
            C[gm * N + gn] = v;
        }
    }
}

// ---------------- fused block-sparse attention (flash-style, 64x64 tiles) ----------------
// logits[i,j] = qc_i . k_j + qr_i . relk[j-i+N-1]   (relative-shift identity)
// mask(i,j)  = (| i/128 - j/128 | <= 1) || i<4 || j<4
#define LDS 65
#define SM_QC 0
#define SM_QR 4160
#define SM_K  8320
#define SM_V  12480
#define SM_RB 16640     // 127*65; P tile aliases this region
#define ATTN_SMEM_FLOATS (16640 + 127 * 65)

__global__ __launch_bounds__(256) void attn_kernel()
{
    extern __shared__ float sm[];
    float* Qcs = sm + SM_QC;
    float* Qrs = sm + SM_QR;
    float* Ks  = sm + SM_K;
    float* Vs  = sm + SM_V;
    float* RBs = sm + SM_RB;
    float* Ps  = sm + SM_RB;   // alias: rel-band dead by the time P is written

    const int qt = blockIdx.x;      // 0..23 query tiles of 64
    const int bh = blockIdx.y;      // 0..15
    const int b  = bh >> 3, h = bh & 7;
    const int i0 = qt * 64;
    const int tid = threadIdx.x;
    const int ty = tid >> 4, tx = tid & 15;
    const int r0 = ty * 4, c0 = tx * 4;

    // load query tiles
    const float* qcg = g_qc + (bh * NSEQ + i0) * DK;
    const float* qrg = g_qr + (bh * NSEQ + i0) * DK;
    for (int idx = tid; idx < 64 * 64; idx += 256) {
        int r = idx >> 6, d = idx & 63;
        Qcs[r * LDS + d] = qcg[r * 64 + d];
        Qrs[r * LDS + d] = qrg[r * 64 + d];
    }

    float m_i[4], l_i[4], O[4][4];
    #pragma unroll
    for (int rr = 0; rr < 4; rr++) {
        m_i[rr] = -1e30f; l_i[rr] = 0.f;
        #pragma unroll
        for (int cc = 0; cc < 4; cc++) O[rr][cc] = 0.f;
    }

    // build key-tile list (block-sparse + global)
    int kts[24]; int nkt = 0;
    const int bi = qt >> 1;
    if (qt == 0) {
        for (int t = 0; t < 24; t++) kts[nkt++] = t;   // global rows 0-3 see everything
    } else {
        int lo = (bi > 0 ? bi - 1 : 0) * 2;
        int hi = (bi < 11 ? bi + 1 : 11) * 2 + 1;
        if (lo > 0) kts[nkt++] = 0;                    // global columns 0-3
        for (int t = lo; t <= hi; t++) kts[nkt++] = t;
    }

    const float* kg = g_k + bh * NSEQ * DK;
    const float* vg = g_v + bh * NSEQ * DK;

    int rbrow[4][4];
    #pragma unroll
    for (int rr = 0; rr < 4; rr++)
        #pragma unroll
        for (int cc = 0; cc < 4; cc++)
            rbrow[rr][cc] = (c0 + cc - r0 - rr + 63) * LDS;

    for (int it = 0; it < nkt; it++) {
        const int j0 = kts[it] * 64;
        __syncthreads();   // previous iteration's P/V reads done before overwrite
        for (int idx = tid; idx < 64 * 64; idx += 256) {
            int r = idx >> 6, d = idx & 63;
            Ks[r * LDS + d] = kg[(j0 + r) * 64 + d];
            Vs[r * LDS + d] = vg[(j0 + r) * 64 + d];
        }
        const int gbase = (j0 - i0) + 1472;   // relk row for band offset 0  (= j0-i0-63+1535)
        for (int idx = tid; idx < 127 * 64; idx += 256) {
            int r = idx >> 6, d = idx & 63;
            RBs[r * LDS + d] = g_relk[(gbase + r) * HD + h * DK + d];
        }
        __syncthreads();

        // S = Qc.K^T + Qr.RelBand
        float S[4][4];
        #pragma unroll
        for (int rr = 0; rr < 4; rr++)
            #pragma unroll
            for (int cc = 0; cc < 4; cc++) S[rr][cc] = 0.f;

        for (int d = 0; d < 64; d++) {
            float qc4[4], qr4[4], k4[4];
            #pragma unroll
            for (int rr = 0; rr < 4; rr++) {
                qc4[rr] = Qcs[(r0 + rr) * LDS + d];
                qr4[rr] = Qrs[(r0 + rr) * LDS + d];
            }
            #pragma unroll
            for (int cc = 0; cc < 4; cc++) k4[cc] = Ks[(c0 + cc) * LDS + d];
            #pragma unroll
            for (int rr = 0; rr < 4; rr++)
                #pragma unroll
                for (int cc = 0; cc < 4; cc++)
                    S[rr][cc] += qc4[rr] * k4[cc] + qr4[rr] * RBs[rbrow[rr][cc] + d];
        }

        // mask
        #pragma unroll
        for (int rr = 0; rr < 4; rr++) {
            int ig = i0 + r0 + rr;
            int bqi = ig >> 7;
            #pragma unroll
            for (int cc = 0; cc < 4; cc++) {
                int jg = j0 + c0 + cc;
                int dlt = bqi - (jg >> 7); if (dlt < 0) dlt = -dlt;
                bool ok = (dlt <= 1) || (ig < 4) || (jg < 4);
                if (!ok) S[rr][cc] = -1e30f;
            }
        }

        // online softmax (row reduction across the 16 tx lanes of the warp)
        float mnew[4], psum[4];
        #pragma unroll
        for (int rr = 0; rr < 4; rr++) {
            float mx = S[rr][0];
            #pragma unroll
            for (int cc = 1; cc < 4; cc++) mx = fmaxf(mx, S[rr][cc]);
            #pragma unroll
            for (int off = 8; off >= 1; off >>= 1)
                mx = fmaxf(mx, __shfl_xor_sync(0xffffffffu, mx, off));
            mnew[rr] = fmaxf(m_i[rr], mx);
            float s = 0.f;
            #pragma unroll
            for (int cc = 0; cc < 4; cc++) {
                float p = __expf(S[rr][cc] - mnew[rr]);
                S[rr][cc] = p; s += p;
            }
            #pragma unroll
            for (int off = 8; off >= 1; off >>= 1)
                s += __shfl_xor_sync(0xffffffffu, s, off);
            psum[rr] = s;
        }

        __syncthreads();   // everyone done reading RBs before P overwrites it
        #pragma unroll
        for (int rr = 0; rr < 4; rr++) {
            float corr = __expf(m_i[rr] - mnew[rr]);
            l_i[rr] = l_i[rr] * corr + psum[rr];
            m_i[rr] = mnew[rr];
            #pragma unroll
            for (int cc = 0; cc < 4; cc++) {
                O[rr][cc] *= corr;
                Ps[(r0 + rr) * LDS + c0 + cc] = S[rr][cc];
            }
        }
        __syncthreads();

        // O += P @ V
        for (int j = 0; j < 64; j++) {
            float p4[4], v4[4];
            #pragma unroll
            for (int rr = 0; rr < 4; rr++) p4[rr] = Ps[(r0 + rr) * LDS + j];
            #pragma unroll
            for (int cc = 0; cc < 4; cc++) v4[cc] = Vs[j * LDS + c0 + cc];
            #pragma unroll
            for (int rr = 0; rr < 4; rr++)
                #pragma unroll
                for (int cc = 0; cc < 4; cc++) O[rr][cc] += p4[rr] * v4[cc];
        }
    }

    // normalize + write [b*n][h*64+d]
    #pragma unroll
    for (int rr = 0; rr < 4; rr++) {
        float inv = 1.f / l_i[rr];
        int ig = i0 + r0 + rr;
        #pragma unroll
        for (int cc = 0; cc < 4; cc++)
            g_ao[(b * NSEQ + ig) * HD + h * DK + c0 + cc] = O[rr][cc] * inv;
    }
}

// ---------------- launch ----------------
extern "C" void kernel_launch(void* const* d_in, const int* in_sizes, int n_in,
                              void* d_out, int out_size)
{
    const float* x    = (const float*)d_in[0];
    const float* Wq   = (const float*)d_in[1];
    const float* Wk   = (const float*)d_in[2];
    const float* Wv   = (const float*)d_in[3];
    const float* Wrel = (const float*)d_in[4];
    const float* rcb  = (const float*)d_in[5];
    const float* rpb  = (const float*)d_in[6];
    const float* Wo   = (const float*)d_in[7];
    const float* bo   = (const float*)d_in[8];
    const float* pe   = (const float*)d_in[9];
    float* out = (float*)d_out;

    void *relk_p = nullptr, *ao_p = nullptr;
    cudaGetSymbolAddress(&relk_p, g_relk);
    cudaGetSymbolAddress(&ao_p, g_ao);

    const int attn_smem = ATTN_SMEM_FLOATS * (int)sizeof(float);   // ~99.6 KB
    cudaFuncSetAttribute(attn_kernel, cudaFuncAttributeMaxDynamicSharedMemorySize, attn_smem);

    // 1. QKV projections (fused 3-way)
    qkv_gemm<<<dim3(4, 24, 3), 256>>>(x, Wq, Wk, Wv, rcb, rpb);

    // 2. rel_k = pos_embed @ Wrel   [3071, 512]
    sgemm_bias<<<dim3(4, 24), 256>>>(pe, Wrel, (float*)relk_p, NPOS, HD, NRPFK, nullptr);

    // 3. fused block-sparse attention with relative-shift term
    attn_kernel<<<dim3(24, 16), 256, attn_smem>>>();

    // 4. output projection + bias
    sgemm_bias<<<dim3(12, 24), 256>>>((const float*)ao_p, Wo, out, BN, DIMX, HD, bo);
}

// round 4
// speedup vs baseline: 1.5606x; 1.5606x over previous
#include <cuda_runtime.h>
#include <math.h>

#define BATCH 2
#define NSEQ 1536
#define DIMX 1536
#define HEADS 8
#define DK 64
#define HD 512
#define BN 3072
#define NPOS 3071
#define NRPFK 192

typedef unsigned long long u64;

__device__ __forceinline__ void fma2(u64 &d, u64 a, u64 b) {
    asm("fma.rn.f32x2 %0, %1, %2, %0;" : "+l"(d) : "l"(a), "l"(b));
}
__device__ __forceinline__ u64 mul2(u64 a, u64 b) {
    u64 r; asm("mul.rn.f32x2 %0, %1, %2;" : "=l"(r) : "l"(a), "l"(b)); return r;
}
__device__ __forceinline__ u64 dup2(float x) {
    u64 r; asm("mov.b64 %0, {%1, %1};" : "=l"(r) : "f"(x)); return r;
}
__device__ __forceinline__ float2 upk(u64 v) {
    float2 r; asm("mov.b64 {%0, %1}, %2;" : "=f"(r.x), "=f"(r.y) : "l"(v)); return r;
}

// ---------------- scratch ----------------
__device__ __align__(16) float g_qc[16 * 1536 * 64];
__device__ __align__(16) float g_qr[16 * 1536 * 64];
__device__ __align__(16) float g_k [16 * 1536 * 64];
__device__ __align__(16) float g_v [16 * 1536 * 64];
__device__ __align__(16) float g_relk[3071 * 512];
__device__ __align__(16) float g_ao[3072 * 512];

// ---------------- fused QKV projection GEMM (FFMA2 core) ----------------
__global__ __launch_bounds__(256) void qkv_gemm(
    const float* __restrict__ x, const float* __restrict__ Wq,
    const float* __restrict__ Wk, const float* __restrict__ Wv,
    const float* __restrict__ rcb, const float* __restrict__ rpb)
{
    const int z = blockIdx.z;
    const float* Bm = (z == 0) ? Wq : (z == 1) ? Wk : Wv;
    const int m0 = blockIdx.y * 128;
    const int n0 = blockIdx.x * 128;

    __shared__ float As[8][128];
    __shared__ float Bs[8][128];

    const int tid  = threadIdx.x;
    const int arow = tid >> 1, akq = (tid & 1) * 4;
    const int bkk  = tid >> 5, bcol = (tid & 31) * 4;
    const int tr   = tid >> 4, tc = tid & 15;

    u64 acc[8][4];
    #pragma unroll
    for (int i = 0; i < 8; i++)
        #pragma unroll
        for (int j = 0; j < 4; j++) acc[i][j] = 0ull;

    for (int k0 = 0; k0 < DIMX; k0 += 8) {
        float4 av = *(const float4*)&x [(m0 + arow) * DIMX + k0 + akq];
        float4 bv = *(const float4*)&Bm[(k0 + bkk) * HD + n0 + bcol];
        __syncthreads();
        As[akq + 0][arow] = av.x; As[akq + 1][arow] = av.y;
        As[akq + 2][arow] = av.z; As[akq + 3][arow] = av.w;
        *(float4*)&Bs[bkk][bcol] = bv;
        __syncthreads();
        #pragma unroll
        for (int kk = 0; kk < 8; kk++) {
            float4 a0 = *(const float4*)&As[kk][tr * 8];
            float4 a1 = *(const float4*)&As[kk][tr * 8 + 4];
            const u64* bp = (const u64*)&Bs[kk][tc * 8];
            u64 b0 = bp[0], b1 = bp[1], b2 = bp[2], b3 = bp[3];
            u64 ad[8] = {dup2(a0.x), dup2(a0.y), dup2(a0.z), dup2(a0.w),
                         dup2(a1.x), dup2(a1.y), dup2(a1.z), dup2(a1.w)};
            #pragma unroll
            for (int i = 0; i < 8; i++) {
                fma2(acc[i][0], ad[i], b0);
                fma2(acc[i][1], ad[i], b1);
                fma2(acc[i][2], ad[i], b2);
                fma2(acc[i][3], ad[i], b3);
            }
        }
    }

    #pragma unroll
    for (int i = 0; i < 8; i++) {
        int gm = m0 + tr * 8 + i;
        int bb = gm / NSEQ;
        int ii = gm - bb * NSEQ;
        #pragma unroll
        for (int cj = 0; cj < 4; cj++) {
            float2 vv = upk(acc[i][cj]);
            float vals[2] = {vv.x, vv.y};
            #pragma unroll
            for (int t = 0; t < 2; t++) {
                int gn = n0 + tc * 8 + cj * 2 + t;
                int hh = gn >> 6, dd = gn & 63;
                int idx = ((bb * HEADS + hh) * NSEQ + ii) * DK + dd;
                float v = vals[t];
                if (z == 0) {
                    g_qc[idx] = v * 0.125f + rcb[gn];
                    g_qr[idx] = v * 0.125f + rpb[gn];
                } else if (z == 1) {
                    g_k[idx] = v;
                } else {
                    g_v[idx] = v;
                }
            }
        }
    }
}

// ---------------- generic SGEMM with optional bias (FFMA2 core) ----------------
__global__ __launch_bounds__(256) void sgemm_bias(
    const float* __restrict__ A, const float* __restrict__ Bm, float* __restrict__ C,
    int M, int N, int K, const float* __restrict__ bias)
{
    const int m0 = blockIdx.y * 128;
    const int n0 = blockIdx.x * 128;

    __shared__ float As[8][128];
    __shared__ float Bs[8][128];

    const int tid  = threadIdx.x;
    const int arow = tid >> 1, akq = (tid & 1) * 4;
    const int bkk  = tid >> 5, bcol = (tid & 31) * 4;
    const int tr   = tid >> 4, tc = tid & 15;

    u64 acc[8][4];
    #pragma unroll
    for (int i = 0; i < 8; i++)
        #pragma unroll
        for (int j = 0; j < 4; j++) acc[i][j] = 0ull;

    for (int k0 = 0; k0 < K; k0 += 8) {
        float4 av = make_float4(0.f, 0.f, 0.f, 0.f);
        if (m0 + arow < M) av = *(const float4*)&A[(m0 + arow) * K + k0 + akq];
        float4 bv = *(const float4*)&Bm[(k0 + bkk) * N + n0 + bcol];
        __syncthreads();
        As[akq + 0][arow] = av.x; As[akq + 1][arow] = av.y;
        As[akq + 2][arow] = av.z; As[akq + 3][arow] = av.w;
        *(float4*)&Bs[bkk][bcol] = bv;
        __syncthreads();
        #pragma unroll
        for (int kk = 0; kk < 8; kk++) {
            float4 a0 = *(const float4*)&As[kk][tr * 8];
            float4 a1 = *(const float4*)&As[kk][tr * 8 + 4];
            const u64* bp = (const u64*)&Bs[kk][tc * 8];
            u64 b0 = bp[0], b1 = bp[1], b2 = bp[2], b3 = bp[3];
            u64 ad[8] = {dup2(a0.x), dup2(a0.y), dup2(a0.z), dup2(a0.w),
                         dup2(a1.x), dup2(a1.y), dup2(a1.z), dup2(a1.w)};
            #pragma unroll
            for (int i = 0; i < 8; i++) {
                fma2(acc[i][0], ad[i], b0);
                fma2(acc[i][1], ad[i], b1);
                fma2(acc[i][2], ad[i], b2);
                fma2(acc[i][3], ad[i], b3);
            }
        }
    }

    #pragma unroll
    for (int i = 0; i < 8; i++) {
        int gm = m0 + tr * 8 + i;
        if (gm >= M) continue;
        #pragma unroll
        for (int cj = 0; cj < 4; cj++) {
            float2 vv = upk(acc[i][cj]);
            float vals[2] = {vv.x, vv.y};
            #pragma unroll
            for (int t = 0; t < 2; t++) {
                int gn = n0 + tc * 8 + cj * 2 + t;
                float v = vals[t];
                if (bias) v += bias[gn];
                C[gm * N + gn] = v;
            }
        }
    }
}

// ---------------- fused block-sparse attention ----------------
// S[i,j] = qc_i.k_j + qr_i.relk[j-i+1535]; mask handled structurally.
#define SM_QC 0
#define SM_QR 4160
#define SM_K  8320            // 64 x 65
#define SM_V  12480           // 64 x 66
#define SM_RB 16704           // 127 x 65 (aliased: Ps 64x66, qt0-phase buffers)
#define SM_S4 24960           // 64 x 4
#define ATTN_SMEM_FLOATS 25216

__global__ __launch_bounds__(256) void attn_kernel()
{
    extern __shared__ float sm[];
    float* Qcs = sm + SM_QC;
    float* Qrs = sm + SM_QR;
    float* Ks  = sm + SM_K;
    float* Vs  = sm + SM_V;
    float* RBs = sm + SM_RB;
    float* Ps  = sm + SM_RB;          // alias
    float* S4buf = sm + SM_S4;

    const int bh = blockIdx.x;        // 0..15
    const int qt = blockIdx.y;        // 0..23
    const int b  = bh >> 3, h = bh & 7;
    const int i0 = qt * 64;
    const int tid = threadIdx.x;
    const int ty = tid >> 4, tx = tid & 15;
    const int r0 = ty * 4, c0 = tx * 4;

    const float* qcg = g_qc + (bh * NSEQ + i0) * DK;
    const float* qrg = g_qr + (bh * NSEQ + i0) * DK;
    for (int idx = tid; idx < 64 * 64; idx += 256) {
        int r = idx >> 6, d = idx & 63;
        Qcs[r * 65 + d] = qcg[r * 64 + d];
        Qrs[r * 65 + d] = qrg[r * 64 + d];
    }

    float m_i[4], l_i[4];
    u64 Op[4][2];
    #pragma unroll
    for (int rr = 0; rr < 4; rr++) {
        m_i[rr] = -1e30f; l_i[rr] = 0.f;
        Op[rr][0] = 0ull; Op[rr][1] = 0ull;
    }

    // key-tile list: all listed tiles are fully inside the mask
    const int bi = qt >> 1;
    int lo, hi;
    if (bi == 0) { lo = 0; hi = 3; }
    else { lo = (bi - 1) * 2; hi = ((bi < 11) ? (bi + 1) : 11) * 2 + 1; }
    const bool do_mini = (lo > 0);      // qt >= 4: global cols 0..3 handled separately
    const bool do_glob = (qt == 0);     // rows 0..3 attend cols 256..1535

    const float* kg = g_k + bh * NSEQ * DK;
    const float* vg = g_v + bh * NSEQ * DK;
    const int base = c0 - r0 + 60;

    for (int t = lo; t <= hi; t++) {
        const int j0 = t * 64;
        __syncthreads();
        for (int idx = tid; idx < 64 * 64; idx += 256) {
            int r = idx >> 6, d = idx & 63;
            Ks[r * 65 + d] = kg[(j0 + r) * 64 + d];
            Vs[r * 66 + d] = vg[(j0 + r) * 64 + d];
        }
        const int gbase = (j0 - i0) + 1472;
        for (int idx = tid; idx < 127 * 64; idx += 256) {
            int r = idx >> 6, d = idx & 63;
            RBs[r * 65 + d] = g_relk[(gbase + r) * HD + h * DK + d];
        }
        __syncthreads();

        float S[4][4];
        #pragma unroll
        for (int rr = 0; rr < 4; rr++)
            #pragma unroll
            for (int cc = 0; cc < 4; cc++) S[rr][cc] = 0.f;

        #pragma unroll 2
        for (int d = 0; d < 64; d++) {
            float rb7[7];
            #pragma unroll
            for (int u = 0; u < 7; u++) rb7[u] = RBs[(base + u) * 65 + d];
            float qc4[4], qr4[4], k4[4];
            #pragma unroll
            for (int rr = 0; rr < 4; rr++) {
                qc4[rr] = Qcs[(r0 + rr) * 65 + d];
                qr4[rr] = Qrs[(r0 + rr) * 65 + d];
            }
            #pragma unroll
            for (int cc = 0; cc < 4; cc++) k4[cc] = Ks[(c0 + cc) * 65 + d];
            #pragma unroll
            for (int rr = 0; rr < 4; rr++)
                #pragma unroll
                for (int cc = 0; cc < 4; cc++)
                    S[rr][cc] += qc4[rr] * k4[cc] + qr4[rr] * rb7[cc - rr + 3];
        }

        // online softmax
        float mnew[4], psum[4];
        #pragma unroll
        for (int rr = 0; rr < 4; rr++) {
            float mx = fmaxf(fmaxf(S[rr][0], S[rr][1]), fmaxf(S[rr][2], S[rr][3]));
            #pragma unroll
            for (int off = 8; off >= 1; off >>= 1)
                mx = fmaxf(mx, __shfl_xor_sync(0xffffffffu, mx, off));
            mnew[rr] = fmaxf(m_i[rr], mx);
            float s = 0.f;
            #pragma unroll
            for (int cc = 0; cc < 4; cc++) {
                float p = __expf(S[rr][cc] - mnew[rr]);
                S[rr][cc] = p; s += p;
            }
            #pragma unroll
            for (int off = 8; off >= 1; off >>= 1)
                s += __shfl_xor_sync(0xffffffffu, s, off);
            psum[rr] = s;
        }

        __syncthreads();
        #pragma unroll
        for (int rr = 0; rr < 4; rr++) {
            float corr = __expf(m_i[rr] - mnew[rr]);
            l_i[rr] = l_i[rr] * corr + psum[rr];
            m_i[rr] = mnew[rr];
            u64 dc = dup2(corr);
            Op[rr][0] = mul2(Op[rr][0], dc);
            Op[rr][1] = mul2(Op[rr][1], dc);
            #pragma unroll
            for (int cc = 0; cc < 4; cc++)
                Ps[(r0 + rr) * 66 + c0 + cc] = S[rr][cc];
        }
        __syncthreads();

        #pragma unroll 2
        for (int j = 0; j < 64; j++) {
            u64 v2a = *(const u64*)&Vs[j * 66 + c0];
            u64 v2b = *(const u64*)&Vs[j * 66 + c0 + 2];
            #pragma unroll
            for (int rr = 0; rr < 4; rr++) {
                u64 dp = dup2(Ps[(r0 + rr) * 66 + j]);
                fma2(Op[rr][0], dp, v2a);
                fma2(Op[rr][1], dp, v2b);
            }
        }
    }

    // ---- mini-phase: global columns 0..3 (qt >= 4) ----
    if (do_mini) {
        __syncthreads();
        if (tid < 256) {
            int r = tid >> 6, d = tid & 63;
            Ks[r * 65 + d] = kg[r * 64 + d];
            Vs[r * 66 + d] = vg[r * 64 + d];
        }
        const int gb2 = 1472 - i0;
        for (int idx = tid; idx < 67 * 64; idx += 256) {
            int r = idx >> 6, d = idx & 63;
            RBs[r * 65 + d] = g_relk[(gb2 + r) * HD + h * DK + d];
        }
        __syncthreads();
        if (tx < 4) {
            int c = tx;
            #pragma unroll
            for (int rr = 0; rr < 4; rr++) {
                float s = 0.f;
                int rbr = (c - r0 - rr + 63) * 65;
                #pragma unroll 8
                for (int d = 0; d < 64; d++)
                    s += Qcs[(r0 + rr) * 65 + d] * Ks[c * 65 + d]
                       + Qrs[(r0 + rr) * 65 + d] * RBs[rbr + d];
                S4buf[(r0 + rr) * 4 + c] = s;
            }
        }
        __syncthreads();
        #pragma unroll
        for (int rr = 0; rr < 4; rr++) {
            float s4[4];
            #pragma unroll
            for (int c = 0; c < 4; c++) s4[c] = S4buf[(r0 + rr) * 4 + c];
            float mx = fmaxf(fmaxf(s4[0], s4[1]), fmaxf(s4[2], s4[3]));
            float mnew = fmaxf(m_i[rr], mx);
            float corr = __expf(m_i[rr] - mnew);
            float p[4]; float ps = 0.f;
            #pragma unroll
            for (int c = 0; c < 4; c++) { p[c] = __expf(s4[c] - mnew); ps += p[c]; }
            l_i[rr] = l_i[rr] * corr + ps;
            m_i[rr] = mnew;
            u64 dc = dup2(corr);
            #pragma unroll
            for (int cj = 0; cj < 2; cj++) {
                u64 o = mul2(Op[rr][cj], dc);
                #pragma unroll
                for (int c = 0; c < 4; c++)
                    fma2(o, dup2(p[c]), *(const u64*)&Vs[c * 66 + c0 + 2 * cj]);
                Op[rr][cj] = o;
            }
        }
    }

    // ---- dense phase: qt==0 rows 0..3 x cols 256..1535 ----
    if (do_glob) {
        __syncthreads();
        float* Sx  = RBs;                 // 4 x 1280
        float* O2  = RBs + 5120;          // 4 x 64
        float* ML  = RBs + 5376;          // M2[0..3], L2[4..7]
        float* wst = RBs + 5384;          // 8 warps x 4 staging

        float mloc[4] = {-1e30f, -1e30f, -1e30f, -1e30f};
        #pragma unroll
        for (int c5 = 0; c5 < 5; c5++) {
            int j = 256 + c5 * 256 + tid;
            const float* kr = kg + j * 64;
            const float* rl = g_relk + (j + 1535) * HD + h * DK;
            float s0 = 0.f, s1 = 0.f, s2 = 0.f, s3 = 0.f;
            #pragma unroll 8
            for (int d = 0; d < 64; d++) {
                float kv = kr[d];
                s0 += Qcs[0 * 65 + d] * kv + Qrs[0 * 65 + d] * rl[d];
                s1 += Qcs[1 * 65 + d] * kv + Qrs[1 * 65 + d] * rl[d - HD];
                s2 += Qcs[2 * 65 + d] * kv + Qrs[2 * 65 + d] * rl[d - 2 * HD];
                s3 += Qcs[3 * 65 + d] * kv + Qrs[3 * 65 + d] * rl[d - 3 * HD];
            }
            int cix = c5 * 256 + tid;
            Sx[0 * 1280 + cix] = s0; Sx[1 * 1280 + cix] = s1;
            Sx[2 * 1280 + cix] = s2; Sx[3 * 1280 + cix] = s3;
            mloc[0] = fmaxf(mloc[0], s0); mloc[1] = fmaxf(mloc[1], s1);
            mloc[2] = fmaxf(mloc[2], s2); mloc[3] = fmaxf(mloc[3], s3);
        }
        #pragma unroll
        for (int r = 0; r < 4; r++)
            #pragma unroll
            for (int off = 16; off >= 1; off >>= 1)
                mloc[r] = fmaxf(mloc[r], __shfl_xor_sync(0xffffffffu, mloc[r], off));
        if ((tid & 31) == 0)
            #pragma unroll
            for (int r = 0; r < 4; r++) wst[(tid >> 5) * 4 + r] = mloc[r];
        __syncthreads();
        if (tid < 4) {
            float m = -1e30f;
            #pragma unroll
            for (int w = 0; w < 8; w++) m = fmaxf(m, wst[w * 4 + tid]);
            ML[tid] = m;
        }
        __syncthreads();
        float M2r[4] = {ML[0], ML[1], ML[2], ML[3]};
        float lloc[4] = {0.f, 0.f, 0.f, 0.f};
        #pragma unroll
        for (int c5 = 0; c5 < 5; c5++) {
            int cix = c5 * 256 + tid;
            #pragma unroll
            for (int r = 0; r < 4; r++) {
                float p = __expf(Sx[r * 1280 + cix] - M2r[r]);
                Sx[r * 1280 + cix] = p;
                lloc[r] += p;
            }
        }
        #pragma unroll
        for (int r = 0; r < 4; r++)
            #pragma unroll
            for (int off = 16; off >= 1; off >>= 1)
                lloc[r] += __shfl_xor_sync(0xffffffffu, lloc[r], off);
        if ((tid & 31) == 0)
            #pragma unroll
            for (int r = 0; r < 4; r++) wst[(tid >> 5) * 4 + r] = lloc[r];
        __syncthreads();
        if (tid < 4) {
            float s = 0.f;
            #pragma unroll
            for (int w = 0; w < 8; w++) s += wst[w * 4 + tid];
            ML[4 + tid] = s;
        }
        __syncthreads();

        // O2[r][c] = sum_j p[r][j] * v[256+j][c]
        {
            int r = tid >> 6, c = tid & 63;
            const float* vp = vg + 256 * 64 + c;
            const float* px = Sx + r * 1280;
            float o = 0.f;
            #pragma unroll 4
            for (int jj = 0; jj < 1280; jj++)
                o += px[jj] * vp[jj * 64];
            O2[r * 64 + c] = o;
        }
        __syncthreads();

        if (ty == 0) {
            #pragma unroll
            for (int rr = 0; rr < 4; rr++) {
                float M2v = ML[rr], L2v = ML[4 + rr];
                float mnew = fmaxf(m_i[rr], M2v);
                float cA = __expf(m_i[rr] - mnew);
                float cB = __expf(M2v - mnew);
                l_i[rr] = l_i[rr] * cA + L2v * cB;
                m_i[rr] = mnew;
                u64 dA = dup2(cA), dB = dup2(cB);
                #pragma unroll
                for (int cj = 0; cj < 2; cj++) {
                    u64 o = mul2(Op[rr][cj], dA);
                    u64 t2 = *(const u64*)&O2[rr * 64 + c0 + 2 * cj];
                    fma2(o, t2, dB);
                    Op[rr][cj] = o;
                }
            }
        }
    }

    // ---- normalize + write ----
    #pragma unroll
    for (int rr = 0; rr < 4; rr++) {
        float inv = 1.f / l_i[rr];
        int ig = i0 + r0 + rr;
        float* op = &g_ao[(b * NSEQ + ig) * HD + h * DK + c0];
        float2 v0 = upk(Op[rr][0]);
        float2 v1 = upk(Op[rr][1]);
        op[0] = v0.x * inv; op[1] = v0.y * inv;
        op[2] = v1.x * inv; op[3] = v1.y * inv;
    }
}

// ---------------- launch ----------------
extern "C" void kernel_launch(void* const* d_in, const int* in_sizes, int n_in,
                              void* d_out, int out_size)
{
    const float* x    = (const float*)d_in[0];
    const float* Wq   = (const float*)d_in[1];
    const float* Wk   = (const float*)d_in[2];
    const float* Wv   = (const float*)d_in[3];
    const float* Wrel = (const float*)d_in[4];
    const float* rcb  = (const float*)d_in[5];
    const float* rpb  = (const float*)d_in[6];
    const float* Wo   = (const float*)d_in[7];
    const float* bo   = (const float*)d_in[8];
    const float* pe   = (const float*)d_in[9];
    float* out = (float*)d_out;

    void *relk_p = nullptr, *ao_p = nullptr;
    cudaGetSymbolAddress(&relk_p, g_relk);
    cudaGetSymbolAddress(&ao_p, g_ao);

    const int attn_smem = ATTN_SMEM_FLOATS * (int)sizeof(float);
    cudaFuncSetAttribute(attn_kernel, cudaFuncAttributeMaxDynamicSharedMemorySize, attn_smem);

    qkv_gemm<<<dim3(4, 24, 3), 256>>>(x, Wq, Wk, Wv, rcb, rpb);
    sgemm_bias<<<dim3(4, 24), 256>>>(pe, Wrel, (float*)relk_p, NPOS, HD, NRPFK, nullptr);
    attn_kernel<<<dim3(16, 24), 256, attn_smem>>>();
    sgemm_bias<<<dim3(12, 24), 256>>>((const float*)ao_p, Wo, out, BN, DIMX, HD, bo);
}

// round 6
// speedup vs baseline: 2.2745x; 1.4575x over previous
#include <cuda_runtime.h>
#include <cuda_bf16.h>
#include <math.h>

#define BATCH 2
#define NSEQ 1536
#define DIMX 1536
#define HEADS 8
#define DK 64
#define HD 512
#define BN 3072
#define NPOS 3071
#define NRPFK 192

typedef unsigned long long u64;
typedef unsigned int u32;

// ================= f32x2 helpers (attention) =================
__device__ __forceinline__ void fma2(u64 &d, u64 a, u64 b) {
    asm("fma.rn.f32x2 %0, %1, %2, %0;" : "+l"(d) : "l"(a), "l"(b));
}
__device__ __forceinline__ u64 mul2(u64 a, u64 b) {
    u64 r; asm("mul.rn.f32x2 %0, %1, %2;" : "=l"(r) : "l"(a), "l"(b)); return r;
}
__device__ __forceinline__ u64 dup2(float x) {
    u64 r; asm("mov.b64 %0, {%1, %1};" : "=l"(r) : "f"(x)); return r;
}
__device__ __forceinline__ float2 upk(u64 v) {
    float2 r; asm("mov.b64 {%0, %1}, %2;" : "=f"(r.x), "=f"(r.y) : "l"(v)); return r;
}

__device__ __forceinline__ u32 smem_u32(const void* p) {
    u32 a;
    asm("{ .reg .u64 t; cvta.to.shared.u64 t, %1; cvt.u32.u64 %0, t; }" : "=r"(a) : "l"(p));
    return a;
}

// ================= warp MMA primitives (baseline sm_80+ path) =================
__device__ __forceinline__ void ldsm4(u32 &r0, u32 &r1, u32 &r2, u32 &r3, u32 addr) {
    asm volatile("ldmatrix.sync.aligned.m8n8.x4.shared.b16 {%0,%1,%2,%3}, [%4];"
                 : "=r"(r0), "=r"(r1), "=r"(r2), "=r"(r3) : "r"(addr));
}
__device__ __forceinline__ void ldsm4t(u32 &r0, u32 &r1, u32 &r2, u32 &r3, u32 addr) {
    asm volatile("ldmatrix.sync.aligned.m8n8.x4.trans.shared.b16 {%0,%1,%2,%3}, [%4];"
                 : "=r"(r0), "=r"(r1), "=r"(r2), "=r"(r3) : "r"(addr));
}
__device__ __forceinline__ void mma16816(float* d, const u32* a, const u32* b) {
    asm volatile("mma.sync.aligned.m16n8k16.row.col.f32.bf16.bf16.f32 "
        "{%0,%1,%2,%3}, {%4,%5,%6,%7}, {%8,%9}, {%0,%1,%2,%3};"
        : "+f"(d[0]), "+f"(d[1]), "+f"(d[2]), "+f"(d[3])
        : "r"(a[0]), "r"(a[1]), "r"(a[2]), "r"(a[3]), "r"(b[0]), "r"(b[1]));
}

// pack two floats -> hi bf16x2 (returned) and lo bf16x2 (out-param)
__device__ __forceinline__ u32 pack2(float x, float y, u32 &lo) {
    __nv_bfloat16 hx = __float2bfloat16(x), hy = __float2bfloat16(y);
    __nv_bfloat16 lx = __float2bfloat16(x - __bfloat162float(hx));
    __nv_bfloat16 ly = __float2bfloat16(y - __bfloat162float(hy));
    lo = (u32)__bfloat16_as_ushort(lx) | ((u32)__bfloat16_as_ushort(ly) << 16);
    return (u32)__bfloat16_as_ushort(hx) | ((u32)__bfloat16_as_ushort(hy) << 16);
}

// ================= scratch =================
__device__ __align__(16) float g_qc[16 * 1536 * 64];
__device__ __align__(16) float g_qr[16 * 1536 * 64];
__device__ __align__(16) float g_k [16 * 1536 * 64];
__device__ __align__(16) float g_v [16 * 1536 * 64];
__device__ __align__(16) float g_relk[3071 * 512];
__device__ __align__(16) float g_ao[3072 * 512];

// ================= GEMM tiling =================
#define BK 32
#define SA_STRIDE 80                 // bytes per A m-row (40 bf16, conflict-free ldmatrix)
#define SA_BYTES (128 * SA_STRIDE)   // 10240
#define SB_BYTES (BK * 256)          // 8192 (k-rows of 128 bf16, xor-swizzled 16B chunks)
#define STAGE_BYTES (2 * SA_BYTES + 2 * SB_BYTES)
#define OFF_A_HI(s) ((s) * STAGE_BYTES)
#define OFF_A_LO(s) (OFF_A_HI(s) + SA_BYTES)
#define OFF_B_HI(s) (OFF_A_HI(s) + 2 * SA_BYTES)
#define OFF_B_LO(s) (OFF_B_HI(s) + SB_BYTES)
#define GEMM_SMEM (2 * STAGE_BYTES)  // 73728 bytes

struct StageRegs { float4 a[4]; float4 b[4]; };

__device__ __forceinline__ void ldg_chunk(StageRegs &R,
    const float* __restrict__ A, int lda, int Mg, int m0,
    const float* __restrict__ B, int ldb, int n0, int kc)
{
    const int t = threadIdx.x;
    {
        int row = t >> 1, kq = (t & 1) * 16;
        bool ok = (m0 + row) < Mg;
        const float* ap = A + (size_t)(m0 + row) * lda + kc * BK + kq;
        #pragma unroll
        for (int i = 0; i < 4; i++)
            R.a[i] = ok ? *(const float4*)(ap + 4 * i) : make_float4(0.f, 0.f, 0.f, 0.f);
    }
    {
        int k = t >> 3, nq = (t & 7) * 16;
        const float* bp = B + (size_t)(kc * BK + k) * ldb + n0 + nq;
        #pragma unroll
        for (int i = 0; i < 4; i++)
            R.b[i] = *(const float4*)(bp + 4 * i);
    }
}

__device__ __forceinline__ void sts_chunk(const StageRegs &R, char* smc, int s)
{
    const int t = threadIdx.x;
    {   // A: [row][k] bf16, 80B stride
        int row = t >> 1, kq = (t & 1) * 16;
        char* ah = smc + OFF_A_HI(s) + row * SA_STRIDE + kq * 2;
        char* al = smc + OFF_A_LO(s) + row * SA_STRIDE + kq * 2;
        #pragma unroll
        for (int i = 0; i < 4; i++) {
            u32 l0, l1;
            u32 h0 = pack2(R.a[i].x, R.a[i].y, l0);
            u32 h1 = pack2(R.a[i].z, R.a[i].w, l1);
            *(u64*)(ah + i * 8) = (u64)h0 | ((u64)h1 << 32);
            *(u64*)(al + i * 8) = (u64)l0 | ((u64)l1 << 32);
        }
    }
    {   // B: [k][n] bf16, 256B rows, 16B chunk xor (k&7)
        int k = t >> 3, nq = (t & 7) * 16;
        char* bh = smc + OFF_B_HI(s) + k * 256;
        char* bl = smc + OFF_B_LO(s) + k * 256;
        int kx = k & 7;
        #pragma unroll
        for (int i = 0; i < 4; i++) {
            int n = nq + 4 * i;
            u32 l0, l1;
            u32 h0 = pack2(R.b[i].x, R.b[i].y, l0);
            u32 h1 = pack2(R.b[i].z, R.b[i].w, l1);
            int off = (((n >> 3) ^ kx) << 4) | ((2 * n) & 15);
            *(u64*)(bh + off) = (u64)h0 | ((u64)h1 << 32);
            *(u64*)(bl + off) = (u64)l0 | ((u64)l1 << 32);
        }
    }
}

__device__ __forceinline__ void mma_chunk(float (&C)[2][8][4], int s, u32 smb)
{
    const int lane = threadIdx.x & 31, wid = threadIdx.x >> 5;
    const int wm = (wid >> 1) * 32, wn = (wid & 1) * 64;
    const u32 aoff[3] = { smb + (u32)OFF_A_HI(s), smb + (u32)OFF_A_HI(s), smb + (u32)OFF_A_LO(s) };
    const u32 boff[3] = { smb + (u32)OFF_B_HI(s), smb + (u32)OFF_B_LO(s), smb + (u32)OFF_B_HI(s) };

    #pragma unroll
    for (int ks = 0; ks < 2; ks++) {
        const int kb = ks * 16;
        #pragma unroll
        for (int p = 0; p < 3; p++) {
            u32 A0[4], A1[4], Bf[8][2];
            {
                int m = wm + (lane & 15);
                int kk = kb + 8 * (lane >> 4);
                ldsm4(A0[0], A0[1], A0[2], A0[3], aoff[p] + m * SA_STRIDE + kk * 2);
                ldsm4(A1[0], A1[1], A1[2], A1[3], aoff[p] + (m + 16) * SA_STRIDE + kk * 2);
            }
            {
                int krow = kb + ((lane >> 3) & 1) * 8 + (lane & 7);
                int nofs = ((lane >> 4) & 1) * 8;
                int kx = krow & 7;
                #pragma unroll
                for (int pr = 0; pr < 4; pr++) {
                    int n = wn + pr * 16 + nofs;
                    u32 addr = boff[p] + krow * 256 + (((n >> 3) ^ kx) << 4);
                    ldsm4t(Bf[2 * pr][0], Bf[2 * pr][1], Bf[2 * pr + 1][0], Bf[2 * pr + 1][1], addr);
                }
            }
            #pragma unroll
            for (int j = 0; j < 8; j++) {
                mma16816(C[0][j], A0, Bf[j]);
                mma16816(C[1][j], A1, Bf[j]);
            }
        }
    }
}

__device__ __forceinline__ void gemm_mma(float (&C)[2][8][4],
    const float* __restrict__ A, int lda, int Mg, int m0,
    const float* __restrict__ B, int ldb, int n0, int K,
    char* smc, u32 smb)
{
    const int NC = K / BK;
    StageRegs R;
    ldg_chunk(R, A, lda, Mg, m0, B, ldb, n0, 0);
    sts_chunk(R, smc, 0);
    __syncthreads();
    for (int c = 0; c < NC; c++) {
        int s = c & 1;
        if (c + 1 < NC) ldg_chunk(R, A, lda, Mg, m0, B, ldb, n0, c + 1);
        mma_chunk(C, s, smb);
        if (c + 1 < NC) sts_chunk(R, smc, s ^ 1);
        __syncthreads();
    }
}

// ================= GEMM kernels =================
__global__ __launch_bounds__(256) void qkv_tc(
    const float* __restrict__ x, const float* __restrict__ Wq,
    const float* __restrict__ Wk, const float* __restrict__ Wv,
    const float* __restrict__ rcb, const float* __restrict__ rpb)
{
    extern __shared__ char smc[];
    u32 smb = smem_u32(smc);
    const int z = blockIdx.z;
    const float* Bm = (z == 0) ? Wq : (z == 1) ? Wk : Wv;
    const int m0 = blockIdx.y * 128, n0 = blockIdx.x * 128;

    float C[2][8][4];
    #pragma unroll
    for (int a = 0; a < 2; a++)
        #pragma unroll
        for (int b = 0; b < 8; b++)
            #pragma unroll
            for (int q = 0; q < 4; q++) C[a][b][q] = 0.f;

    gemm_mma(C, x, DIMX, BN, m0, Bm, HD, n0, DIMX, smc, smb);

    const int lane = threadIdx.x & 31, wid = threadIdx.x >> 5;
    const int wm = m0 + (wid >> 1) * 32, wn = n0 + (wid & 1) * 64;
    #pragma unroll
    for (int t2 = 0; t2 < 2; t2++)
        #pragma unroll
        for (int j = 0; j < 8; j++)
            #pragma unroll
            for (int hf = 0; hf < 2; hf++) {
                int gm = wm + 16 * t2 + (lane >> 2) + 8 * hf;
                int gn = wn + 8 * j + 2 * (lane & 3);
                float v0 = C[t2][j][2 * hf], v1 = C[t2][j][2 * hf + 1];
                int bb = gm / NSEQ, ii = gm - bb * NSEQ;
                int hh = gn >> 6, dd = gn & 63;
                int idx = ((bb * HEADS + hh) * NSEQ + ii) * DK + dd;
                if (z == 0) {
                    float2 cb = *(const float2*)&rcb[gn];
                    float2 pb = *(const float2*)&rpb[gn];
                    *(float2*)&g_qc[idx] = make_float2(v0 * 0.125f + cb.x, v1 * 0.125f + cb.y);
                    *(float2*)&g_qr[idx] = make_float2(v0 * 0.125f + pb.x, v1 * 0.125f + pb.y);
                } else if (z == 1) {
                    *(float2*)&g_k[idx] = make_float2(v0, v1);
                } else {
                    *(float2*)&g_v[idx] = make_float2(v0, v1);
                }
            }
}

__global__ __launch_bounds__(256) void relk_tc(
    const float* __restrict__ pe, const float* __restrict__ Wrel)
{
    extern __shared__ char smc[];
    u32 smb = smem_u32(smc);
    const int m0 = blockIdx.y * 128, n0 = blockIdx.x * 128;

    float C[2][8][4];
    #pragma unroll
    for (int a = 0; a < 2; a++)
        #pragma unroll
        for (int b = 0; b < 8; b++)
            #pragma unroll
            for (int q = 0; q < 4; q++) C[a][b][q] = 0.f;

    gemm_mma(C, pe, NRPFK, NPOS, m0, Wrel, HD, n0, NRPFK, smc, smb);

    const int lane = threadIdx.x & 31, wid = threadIdx.x >> 5;
    const int wm = m0 + (wid >> 1) * 32, wn = n0 + (wid & 1) * 64;
    #pragma unroll
    for (int t2 = 0; t2 < 2; t2++)
        #pragma unroll
        for (int j = 0; j < 8; j++)
            #pragma unroll
            for (int hf = 0; hf < 2; hf++) {
                int gm = wm + 16 * t2 + (lane >> 2) + 8 * hf;
                int gn = wn + 8 * j + 2 * (lane & 3);
                if (gm < NPOS)
                    *(float2*)&g_relk[(size_t)gm * HD + gn] =
                        make_float2(C[t2][j][2 * hf], C[t2][j][2 * hf + 1]);
            }
}

__global__ __launch_bounds__(256) void out_tc(
    const float* __restrict__ Wo, const float* __restrict__ bo, float* __restrict__ out)
{
    extern __shared__ char smc[];
    u32 smb = smem_u32(smc);
    const int m0 = blockIdx.y * 128, n0 = blockIdx.x * 128;

    float C[2][8][4];
    #pragma unroll
    for (int a = 0; a < 2; a++)
        #pragma unroll
        for (int b = 0; b < 8; b++)
            #pragma unroll
            for (int q = 0; q < 4; q++) C[a][b][q] = 0.f;

    gemm_mma(C, g_ao, HD, BN, m0, Wo, DIMX, n0, HD, smc, smb);

    const int lane = threadIdx.x & 31, wid = threadIdx.x >> 5;
    const int wm = m0 + (wid >> 1) * 32, wn = n0 + (wid & 1) * 64;
    #pragma unroll
    for (int t2 = 0; t2 < 2; t2++)
        #pragma unroll
        for (int j = 0; j < 8; j++)
            #pragma unroll
            for (int hf = 0; hf < 2; hf++) {
                int gm = wm + 16 * t2 + (lane >> 2) + 8 * hf;
                int gn = wn + 8 * j + 2 * (lane & 3);
                float2 bv = *(const float2*)&bo[gn];
                *(float2*)&out[(size_t)gm * DIMX + gn] =
                    make_float2(C[t2][j][2 * hf] + bv.x, C[t2][j][2 * hf + 1] + bv.y);
            }
}

// ================= fused block-sparse attention (unchanged) =================
#define SM_QC 0
#define SM_QR 4160
#define SM_K  8320
#define SM_V  12480
#define SM_RB 16704
#define SM_S4 24960
#define ATTN_SMEM_FLOATS 25216

__global__ __launch_bounds__(256) void attn_kernel()
{
    extern __shared__ float sm[];
    float* Qcs = sm + SM_QC;
    float* Qrs = sm + SM_QR;
    float* Ks  = sm + SM_K;
    float* Vs  = sm + SM_V;
    float* RBs = sm + SM_RB;
    float* Ps  = sm + SM_RB;
    float* S4buf = sm + SM_S4;

    const int bh = blockIdx.x;
    const int qt = blockIdx.y;
    const int b  = bh >> 3, h = bh & 7;
    const int i0 = qt * 64;
    const int tid = threadIdx.x;
    const int ty = tid >> 4, tx = tid & 15;
    const int r0 = ty * 4, c0 = tx * 4;

    const float* qcg = g_qc + (bh * NSEQ + i0) * DK;
    const float* qrg = g_qr + (bh * NSEQ + i0) * DK;
    for (int idx = tid; idx < 64 * 64; idx += 256) {
        int r = idx >> 6, d = idx & 63;
        Qcs[r * 65 + d] = qcg[r * 64 + d];
        Qrs[r * 65 + d] = qrg[r * 64 + d];
    }

    float m_i[4], l_i[4];
    u64 Op[4][2];
    #pragma unroll
    for (int rr = 0; rr < 4; rr++) {
        m_i[rr] = -1e30f; l_i[rr] = 0.f;
        Op[rr][0] = 0ull; Op[rr][1] = 0ull;
    }

    const int bi = qt >> 1;
    int lo, hi;
    if (bi == 0) { lo = 0; hi = 3; }
    else { lo = (bi - 1) * 2; hi = ((bi < 11) ? (bi + 1) : 11) * 2 + 1; }
    const bool do_mini = (lo > 0);
    const bool do_glob = (qt == 0);

    const float* kg = g_k + bh * NSEQ * DK;
    const float* vg = g_v + bh * NSEQ * DK;
    const int base = c0 - r0 + 60;

    for (int t = lo; t <= hi; t++) {
        const int j0 = t * 64;
        __syncthreads();
        for (int idx = tid; idx < 64 * 64; idx += 256) {
            int r = idx >> 6, d = idx & 63;
            Ks[r * 65 + d] = kg[(j0 + r) * 64 + d];
            Vs[r * 66 + d] = vg[(j0 + r) * 64 + d];
        }
        const int gbase = (j0 - i0) + 1472;
        for (int idx = tid; idx < 127 * 64; idx += 256) {
            int r = idx >> 6, d = idx & 63;
            RBs[r * 65 + d] = g_relk[(gbase + r) * HD + h * DK + d];
        }
        __syncthreads();

        float S[4][4];
        #pragma unroll
        for (int rr = 0; rr < 4; rr++)
            #pragma unroll
            for (int cc = 0; cc < 4; cc++) S[rr][cc] = 0.f;

        #pragma unroll 2
        for (int d = 0; d < 64; d++) {
            float rb7[7];
            #pragma unroll
            for (int u = 0; u < 7; u++) rb7[u] = RBs[(base + u) * 65 + d];
            float qc4[4], qr4[4], k4[4];
            #pragma unroll
            for (int rr = 0; rr < 4; rr++) {
                qc4[rr] = Qcs[(r0 + rr) * 65 + d];
                qr4[rr] = Qrs[(r0 + rr) * 65 + d];
            }
            #pragma unroll
            for (int cc = 0; cc < 4; cc++) k4[cc] = Ks[(c0 + cc) * 65 + d];
            #pragma unroll
            for (int rr = 0; rr < 4; rr++)
                #pragma unroll
                for (int cc = 0; cc < 4; cc++)
                    S[rr][cc] += qc4[rr] * k4[cc] + qr4[rr] * rb7[cc - rr + 3];
        }

        float mnew[4], psum[4];
        #pragma unroll
        for (int rr = 0; rr < 4; rr++) {
            float mx = fmaxf(fmaxf(S[rr][0], S[rr][1]), fmaxf(S[rr][2], S[rr][3]));
            #pragma unroll
            for (int off = 8; off >= 1; off >>= 1)
                mx = fmaxf(mx, __shfl_xor_sync(0xffffffffu, mx, off));
            mnew[rr] = fmaxf(m_i[rr], mx);
            float s = 0.f;
            #pragma unroll
            for (int cc = 0; cc < 4; cc++) {
                float p = __expf(S[rr][cc] - mnew[rr]);
                S[rr][cc] = p; s += p;
            }
            #pragma unroll
            for (int off = 8; off >= 1; off >>= 1)
                s += __shfl_xor_sync(0xffffffffu, s, off);
            psum[rr] = s;
        }

        __syncthreads();
        #pragma unroll
        for (int rr = 0; rr < 4; rr++) {
            float corr = __expf(m_i[rr] - mnew[rr]);
            l_i[rr] = l_i[rr] * corr + psum[rr];
            m_i[rr] = mnew[rr];
            u64 dc = dup2(corr);
            Op[rr][0] = mul2(Op[rr][0], dc);
            Op[rr][1] = mul2(Op[rr][1], dc);
            #pragma unroll
            for (int cc = 0; cc < 4; cc++)
                Ps[(r0 + rr) * 66 + c0 + cc] = S[rr][cc];
        }
        __syncthreads();

        #pragma unroll 2
        for (int j = 0; j < 64; j++) {
            u64 v2a = *(const u64*)&Vs[j * 66 + c0];
            u64 v2b = *(const u64*)&Vs[j * 66 + c0 + 2];
            #pragma unroll
            for (int rr = 0; rr < 4; rr++) {
                u64 dp = dup2(Ps[(r0 + rr) * 66 + j]);
                fma2(Op[rr][0], dp, v2a);
                fma2(Op[rr][1], dp, v2b);
            }
        }
    }

    if (do_mini) {
        __syncthreads();
        if (tid < 256) {
            int r = tid >> 6, d = tid & 63;
            Ks[r * 65 + d] = kg[r * 64 + d];
            Vs[r * 66 + d] = vg[r * 64 + d];
        }
        const int gb2 = 1472 - i0;
        for (int idx = tid; idx < 67 * 64; idx += 256) {
            int r = idx >> 6, d = idx & 63;
            RBs[r * 65 + d] = g_relk[(gb2 + r) * HD + h * DK + d];
        }
        __syncthreads();
        if (tx < 4) {
            int c = tx;
            #pragma unroll
            for (int rr = 0; rr < 4; rr++) {
                float s = 0.f;
                int rbr = (c - r0 - rr + 63) * 65;
                #pragma unroll 8
                for (int d = 0; d < 64; d++)
                    s += Qcs[(r0 + rr) * 65 + d] * Ks[c * 65 + d]
                       + Qrs[(r0 + rr) * 65 + d] * RBs[rbr + d];
                S4buf[(r0 + rr) * 4 + c] = s;
            }
        }
        __syncthreads();
        #pragma unroll
        for (int rr = 0; rr < 4; rr++) {
            float s4[4];
            #pragma unroll
            for (int c = 0; c < 4; c++) s4[c] = S4buf[(r0 + rr) * 4 + c];
            float mx = fmaxf(fmaxf(s4[0], s4[1]), fmaxf(s4[2], s4[3]));
            float mnew = fmaxf(m_i[rr], mx);
            float corr = __expf(m_i[rr] - mnew);
            float p[4]; float ps = 0.f;
            #pragma unroll
            for (int c = 0; c < 4; c++) { p[c] = __expf(s4[c] - mnew); ps += p[c]; }
            l_i[rr] = l_i[rr] * corr + ps;
            m_i[rr] = mnew;
            u64 dc = dup2(corr);
            #pragma unroll
            for (int cj = 0; cj < 2; cj++) {
                u64 o = mul2(Op[rr][cj], dc);
                #pragma unroll
                for (int c = 0; c < 4; c++)
                    fma2(o, dup2(p[c]), *(const u64*)&Vs[c * 66 + c0 + 2 * cj]);
                Op[rr][cj] = o;
            }
        }
    }

    if (do_glob) {
        __syncthreads();
        float* Sx  = RBs;
        float* O2  = RBs + 5120;
        float* ML  = RBs + 5376;
        float* wst = RBs + 5384;

        float mloc[4] = {-1e30f, -1e30f, -1e30f, -1e30f};
        #pragma unroll
        for (int c5 = 0; c5 < 5; c5++) {
            int j = 256 + c5 * 256 + tid;
            const float* kr = kg + j * 64;
            const float* rl = g_relk + (size_t)(j + 1535) * HD + h * DK;
            float s0 = 0.f, s1 = 0.f, s2 = 0.f, s3 = 0.f;
            #pragma unroll 8
            for (int d = 0; d < 64; d++) {
                float kv = kr[d];
                s0 += Qcs[0 * 65 + d] * kv + Qrs[0 * 65 + d] * rl[d];
                s1 += Qcs[1 * 65 + d] * kv + Qrs[1 * 65 + d] * rl[d - HD];
                s2 += Qcs[2 * 65 + d] * kv + Qrs[2 * 65 + d] * rl[d - 2 * HD];
                s3 += Qcs[3 * 65 + d] * kv + Qrs[3 * 65 + d] * rl[d - 3 * HD];
            }
            int cix = c5 * 256 + tid;
            Sx[0 * 1280 + cix] = s0; Sx[1 * 1280 + cix] = s1;
            Sx[2 * 1280 + cix] = s2; Sx[3 * 1280 + cix] = s3;
            mloc[0] = fmaxf(mloc[0], s0); mloc[1] = fmaxf(mloc[1], s1);
            mloc[2] = fmaxf(mloc[2], s2); mloc[3] = fmaxf(mloc[3], s3);
        }
        #pragma unroll
        for (int r = 0; r < 4; r++)
            #pragma unroll
            for (int off = 16; off >= 1; off >>= 1)
                mloc[r] = fmaxf(mloc[r], __shfl_xor_sync(0xffffffffu, mloc[r], off));
        if ((tid & 31) == 0)
            #pragma unroll
            for (int r = 0; r < 4; r++) wst[(tid >> 5) * 4 + r] = mloc[r];
        __syncthreads();
        if (tid < 4) {
            float m = -1e30f;
            #pragma unroll
            for (int w = 0; w < 8; w++) m = fmaxf(m, wst[w * 4 + tid]);
            ML[tid] = m;
        }
        __syncthreads();
        float M2r[4] = {ML[0], ML[1], ML[2], ML[3]};
        float lloc[4] = {0.f, 0.f, 0.f, 0.f};
        #pragma unroll
        for (int c5 = 0; c5 < 5; c5++) {
            int cix = c5 * 256 + tid;
            #pragma unroll
            for (int r = 0; r < 4; r++) {
                float p = __expf(Sx[r * 1280 + cix] - M2r[r]);
                Sx[r * 1280 + cix] = p;
                lloc[r] += p;
            }
        }
        #pragma unroll
        for (int r = 0; r < 4; r++)
            #pragma unroll
            for (int off = 16; off >= 1; off >>= 1)
                lloc[r] += __shfl_xor_sync(0xffffffffu, lloc[r], off);
        if ((tid & 31) == 0)
            #pragma unroll
            for (int r = 0; r < 4; r++) wst[(tid >> 5) * 4 + r] = lloc[r];
        __syncthreads();
        if (tid < 4) {
            float s = 0.f;
            #pragma unroll
            for (int w = 0; w < 8; w++) s += wst[w * 4 + tid];
            ML[4 + tid] = s;
        }
        __syncthreads();

        {
            int r = tid >> 6, c = tid & 63;
            const float* vp = vg + 256 * 64 + c;
            const float* px = Sx + r * 1280;
            float o = 0.f;
            #pragma unroll 4
            for (int jj = 0; jj < 1280; jj++)
                o += px[jj] * vp[jj * 64];
            O2[r * 64 + c] = o;
        }
        __syncthreads();

        if (ty == 0) {
            #pragma unroll
            for (int rr = 0; rr < 4; rr++) {
                float M2v = ML[rr], L2v = ML[4 + rr];
                float mnew = fmaxf(m_i[rr], M2v);
                float cA = __expf(m_i[rr] - mnew);
                float cB = __expf(M2v - mnew);
                l_i[rr] = l_i[rr] * cA + L2v * cB;
                m_i[rr] = mnew;
                u64 dA = dup2(cA), dB = dup2(cB);
                #pragma unroll
                for (int cj = 0; cj < 2; cj++) {
                    u64 o = mul2(Op[rr][cj], dA);
                    u64 t2 = *(const u64*)&O2[rr * 64 + c0 + 2 * cj];
                    fma2(o, t2, dB);
                    Op[rr][cj] = o;
                }
            }
        }
    }

    #pragma unroll
    for (int rr = 0; rr < 4; rr++) {
        float inv = 1.f / l_i[rr];
        int ig = i0 + r0 + rr;
        float* op = &g_ao[(b * NSEQ + ig) * HD + h * DK + c0];
        float2 v0 = upk(Op[rr][0]);
        float2 v1 = upk(Op[rr][1]);
        op[0] = v0.x * inv; op[1] = v0.y * inv;
        op[2] = v1.x * inv; op[3] = v1.y * inv;
    }
}

// ================= launch =================
extern "C" void kernel_launch(void* const* d_in, const int* in_sizes, int n_in,
                              void* d_out, int out_size)
{
    const float* x    = (const float*)d_in[0];
    const float* Wq   = (const float*)d_in[1];
    const float* Wk   = (const float*)d_in[2];
    const float* Wv   = (const float*)d_in[3];
    const float* Wrel = (const float*)d_in[4];
    const float* rcb  = (const float*)d_in[5];
    const float* rpb  = (const float*)d_in[6];
    const float* Wo   = (const float*)d_in[7];
    const float* bo   = (const float*)d_in[8];
    const float* pe   = (const float*)d_in[9];
    float* out = (float*)d_out;

    const int attn_smem = ATTN_SMEM_FLOATS * (int)sizeof(float);
    cudaFuncSetAttribute(attn_kernel, cudaFuncAttributeMaxDynamicSharedMemorySize, attn_smem);
    cudaFuncSetAttribute(qkv_tc,  cudaFuncAttributeMaxDynamicSharedMemorySize, GEMM_SMEM);
    cudaFuncSetAttribute(relk_tc, cudaFuncAttributeMaxDynamicSharedMemorySize, GEMM_SMEM);
    cudaFuncSetAttribute(out_tc,  cudaFuncAttributeMaxDynamicSharedMemorySize, GEMM_SMEM);

    qkv_tc <<<dim3(4, 24, 3), 256, GEMM_SMEM>>>(x, Wq, Wk, Wv, rcb, rpb);
    relk_tc<<<dim3(4, 24),    256, GEMM_SMEM>>>(pe, Wrel);
    attn_kernel<<<dim3(16, 24), 256, attn_smem>>>();
    out_tc <<<dim3(12, 24),   256, GEMM_SMEM>>>(Wo, bo, out);
}

// round 7
// speedup vs baseline: 2.4342x; 1.0702x over previous
#include <cuda_runtime.h>
#include <cuda_bf16.h>
#include <math.h>

#define BATCH 2
#define NSEQ 1536
#define DIMX 1536
#define HEADS 8
#define DK 64
#define HD 512
#define BN 3072
#define NPOS 3071
#define NRPFK 192

typedef unsigned long long u64;
typedef unsigned int u32;

__device__ __forceinline__ u32 smem_u32(const void* p) {
    u32 a;
    asm("{ .reg .u64 t; cvta.to.shared.u64 t, %1; cvt.u32.u64 %0, t; }" : "=r"(a) : "l"(p));
    return a;
}

// ================= warp MMA primitives (baseline sm_80+ path) =================
__device__ __forceinline__ void ldsm4(u32 &r0, u32 &r1, u32 &r2, u32 &r3, u32 addr) {
    asm volatile("ldmatrix.sync.aligned.m8n8.x4.shared.b16 {%0,%1,%2,%3}, [%4];"
                 : "=r"(r0), "=r"(r1), "=r"(r2), "=r"(r3) : "r"(addr));
}
__device__ __forceinline__ void ldsm4t(u32 &r0, u32 &r1, u32 &r2, u32 &r3, u32 addr) {
    asm volatile("ldmatrix.sync.aligned.m8n8.x4.trans.shared.b16 {%0,%1,%2,%3}, [%4];"
                 : "=r"(r0), "=r"(r1), "=r"(r2), "=r"(r3) : "r"(addr));
}
__device__ __forceinline__ void mma16816(float* d, const u32* a, const u32* b) {
    asm volatile("mma.sync.aligned.m16n8k16.row.col.f32.bf16.bf16.f32 "
        "{%0,%1,%2,%3}, {%4,%5,%6,%7}, {%8,%9}, {%0,%1,%2,%3};"
        : "+f"(d[0]), "+f"(d[1]), "+f"(d[2]), "+f"(d[3])
        : "r"(a[0]), "r"(a[1]), "r"(a[2]), "r"(a[3]), "r"(b[0]), "r"(b[1]));
}

// pack two floats -> hi bf16x2 (returned) and lo bf16x2 (out-param)
__device__ __forceinline__ u32 pack2(float x, float y, u32 &lo) {
    __nv_bfloat16 hx = __float2bfloat16(x), hy = __float2bfloat16(y);
    __nv_bfloat16 lx = __float2bfloat16(x - __bfloat162float(hx));
    __nv_bfloat16 ly = __float2bfloat16(y - __bfloat162float(hy));
    lo = (u32)__bfloat16_as_ushort(lx) | ((u32)__bfloat16_as_ushort(ly) << 16);
    return (u32)__bfloat16_as_ushort(hx) | ((u32)__bfloat16_as_ushort(hy) << 16);
}

// ================= scratch =================
__device__ __align__(16) float g_qc[16 * 1536 * 64];
__device__ __align__(16) float g_qr[16 * 1536 * 64];
__device__ __align__(16) float g_k [16 * 1536 * 64];
__device__ __align__(16) float g_v [16 * 1536 * 64];
__device__ __align__(16) float g_relk[3071 * 512];
__device__ __align__(16) float g_ao[3072 * 512];

// ================= GEMM tiling (unchanged from R6) =================
#define BK 32
#define SA_STRIDE 80
#define SA_BYTES (128 * SA_STRIDE)
#define SB_BYTES (BK * 256)
#define STAGE_BYTES (2 * SA_BYTES + 2 * SB_BYTES)
#define OFF_A_HI(s) ((s) * STAGE_BYTES)
#define OFF_A_LO(s) (OFF_A_HI(s) + SA_BYTES)
#define OFF_B_HI(s) (OFF_A_HI(s) + 2 * SA_BYTES)
#define OFF_B_LO(s) (OFF_B_HI(s) + SB_BYTES)
#define GEMM_SMEM (2 * STAGE_BYTES)

struct StageRegs { float4 a[4]; float4 b[4]; };

__device__ __forceinline__ void ldg_chunk(StageRegs &R,
    const float* __restrict__ A, int lda, int Mg, int m0,
    const float* __restrict__ B, int ldb, int n0, int kc)
{
    const int t = threadIdx.x;
    {
        int row = t >> 1, kq = (t & 1) * 16;
        bool ok = (m0 + row) < Mg;
        const float* ap = A + (size_t)(m0 + row) * lda + kc * BK + kq;
        #pragma unroll
        for (int i = 0; i < 4; i++)
            R.a[i] = ok ? *(const float4*)(ap + 4 * i) : make_float4(0.f, 0.f, 0.f, 0.f);
    }
    {
        int k = t >> 3, nq = (t & 7) * 16;
        const float* bp = B + (size_t)(kc * BK + k) * ldb + n0 + nq;
        #pragma unroll
        for (int i = 0; i < 4; i++)
            R.b[i] = *(const float4*)(bp + 4 * i);
    }
}

__device__ __forceinline__ void sts_chunk(const StageRegs &R, char* smc, int s)
{
    const int t = threadIdx.x;
    {
        int row = t >> 1, kq = (t & 1) * 16;
        char* ah = smc + OFF_A_HI(s) + row * SA_STRIDE + kq * 2;
        char* al = smc + OFF_A_LO(s) + row * SA_STRIDE + kq * 2;
        #pragma unroll
        for (int i = 0; i < 4; i++) {
            u32 l0, l1;
            u32 h0 = pack2(R.a[i].x, R.a[i].y, l0);
            u32 h1 = pack2(R.a[i].z, R.a[i].w, l1);
            *(u64*)(ah + i * 8) = (u64)h0 | ((u64)h1 << 32);
            *(u64*)(al + i * 8) = (u64)l0 | ((u64)l1 << 32);
        }
    }
    {
        int k = t >> 3, nq = (t & 7) * 16;
        char* bh = smc + OFF_B_HI(s) + k * 256;
        char* bl = smc + OFF_B_LO(s) + k * 256;
        int kx = k & 7;
        #pragma unroll
        for (int i = 0; i < 4; i++) {
            int n = nq + 4 * i;
            u32 l0, l1;
            u32 h0 = pack2(R.b[i].x, R.b[i].y, l0);
            u32 h1 = pack2(R.b[i].z, R.b[i].w, l1);
            int off = (((n >> 3) ^ kx) << 4) | ((2 * n) & 15);
            *(u64*)(bh + off) = (u64)h0 | ((u64)h1 << 32);
            *(u64*)(bl + off) = (u64)l0 | ((u64)l1 << 32);
        }
    }
}

__device__ __forceinline__ void mma_chunk(float (&C)[2][8][4], int s, u32 smb)
{
    const int lane = threadIdx.x & 31, wid = threadIdx.x >> 5;
    const int wm = (wid >> 1) * 32, wn = (wid & 1) * 64;
    const u32 aoff[3] = { smb + (u32)OFF_A_HI(s), smb + (u32)OFF_A_HI(s), smb + (u32)OFF_A_LO(s) };
    const u32 boff[3] = { smb + (u32)OFF_B_HI(s), smb + (u32)OFF_B_LO(s), smb + (u32)OFF_B_HI(s) };

    #pragma unroll
    for (int ks = 0; ks < 2; ks++) {
        const int kb = ks * 16;
        #pragma unroll
        for (int p = 0; p < 3; p++) {
            u32 A0[4], A1[4], Bf[8][2];
            {
                int m = wm + (lane & 15);
                int kk = kb + 8 * (lane >> 4);
                ldsm4(A0[0], A0[1], A0[2], A0[3], aoff[p] + m * SA_STRIDE + kk * 2);
                ldsm4(A1[0], A1[1], A1[2], A1[3], aoff[p] + (m + 16) * SA_STRIDE + kk * 2);
            }
            {
                int krow = kb + ((lane >> 3) & 1) * 8 + (lane & 7);
                int nofs = ((lane >> 4) & 1) * 8;
                int kx = krow & 7;
                #pragma unroll
                for (int pr = 0; pr < 4; pr++) {
                    int n = wn + pr * 16 + nofs;
                    u32 addr = boff[p] + krow * 256 + (((n >> 3) ^ kx) << 4);
                    ldsm4t(Bf[2 * pr][0], Bf[2 * pr][1], Bf[2 * pr + 1][0], Bf[2 * pr + 1][1], addr);
                }
            }
            #pragma unroll
            for (int j = 0; j < 8; j++) {
                mma16816(C[0][j], A0, Bf[j]);
                mma16816(C[1][j], A1, Bf[j]);
            }
        }
    }
}

__device__ __forceinline__ void gemm_mma(float (&C)[2][8][4],
    const float* __restrict__ A, int lda, int Mg, int m0,
    const float* __restrict__ B, int ldb, int n0, int K,
    char* smc, u32 smb)
{
    const int NC = K / BK;
    StageRegs R;
    ldg_chunk(R, A, lda, Mg, m0, B, ldb, n0, 0);
    sts_chunk(R, smc, 0);
    __syncthreads();
    for (int c = 0; c < NC; c++) {
        int s = c & 1;
        if (c + 1 < NC) ldg_chunk(R, A, lda, Mg, m0, B, ldb, n0, c + 1);
        mma_chunk(C, s, smb);
        if (c + 1 < NC) sts_chunk(R, smc, s ^ 1);
        __syncthreads();
    }
}

// ================= GEMM kernels =================
__global__ __launch_bounds__(256) void qkv_tc(
    const float* __restrict__ x, const float* __restrict__ Wq,
    const float* __restrict__ Wk, const float* __restrict__ Wv,
    const float* __restrict__ rcb, const float* __restrict__ rpb)
{
    extern __shared__ char smc[];
    u32 smb = smem_u32(smc);
    const int z = blockIdx.z;
    const float* Bm = (z == 0) ? Wq : (z == 1) ? Wk : Wv;
    const int m0 = blockIdx.y * 128, n0 = blockIdx.x * 128;

    float C[2][8][4];
    #pragma unroll
    for (int a = 0; a < 2; a++)
        #pragma unroll
        for (int b = 0; b < 8; b++)
            #pragma unroll
            for (int q = 0; q < 4; q++) C[a][b][q] = 0.f;

    gemm_mma(C, x, DIMX, BN, m0, Bm, HD, n0, DIMX, smc, smb);

    const int lane = threadIdx.x & 31, wid = threadIdx.x >> 5;
    const int wm = m0 + (wid >> 1) * 32, wn = n0 + (wid & 1) * 64;
    #pragma unroll
    for (int t2 = 0; t2 < 2; t2++)
        #pragma unroll
        for (int j = 0; j < 8; j++)
            #pragma unroll
            for (int hf = 0; hf < 2; hf++) {
                int gm = wm + 16 * t2 + (lane >> 2) + 8 * hf;
                int gn = wn + 8 * j + 2 * (lane & 3);
                float v0 = C[t2][j][2 * hf], v1 = C[t2][j][2 * hf + 1];
                int bb = gm / NSEQ, ii = gm - bb * NSEQ;
                int hh = gn >> 6, dd = gn & 63;
                int idx = ((bb * HEADS + hh) * NSEQ + ii) * DK + dd;
                if (z == 0) {
                    float2 cb = *(const float2*)&rcb[gn];
                    float2 pb = *(const float2*)&rpb[gn];
                    *(float2*)&g_qc[idx] = make_float2(v0 * 0.125f + cb.x, v1 * 0.125f + cb.y);
                    *(float2*)&g_qr[idx] = make_float2(v0 * 0.125f + pb.x, v1 * 0.125f + pb.y);
                } else if (z == 1) {
                    *(float2*)&g_k[idx] = make_float2(v0, v1);
                } else {
                    *(float2*)&g_v[idx] = make_float2(v0, v1);
                }
            }
}

__global__ __launch_bounds__(256) void relk_tc(
    const float* __restrict__ pe, const float* __restrict__ Wrel)
{
    extern __shared__ char smc[];
    u32 smb = smem_u32(smc);
    const int m0 = blockIdx.y * 128, n0 = blockIdx.x * 128;

    float C[2][8][4];
    #pragma unroll
    for (int a = 0; a < 2; a++)
        #pragma unroll
        for (int b = 0; b < 8; b++)
            #pragma unroll
            for (int q = 0; q < 4; q++) C[a][b][q] = 0.f;

    gemm_mma(C, pe, NRPFK, NPOS, m0, Wrel, HD, n0, NRPFK, smc, smb);

    const int lane = threadIdx.x & 31, wid = threadIdx.x >> 5;
    const int wm = m0 + (wid >> 1) * 32, wn = n0 + (wid & 1) * 64;
    #pragma unroll
    for (int t2 = 0; t2 < 2; t2++)
        #pragma unroll
        for (int j = 0; j < 8; j++)
            #pragma unroll
            for (int hf = 0; hf < 2; hf++) {
                int gm = wm + 16 * t2 + (lane >> 2) + 8 * hf;
                int gn = wn + 8 * j + 2 * (lane & 3);
                if (gm < NPOS)
                    *(float2*)&g_relk[(size_t)gm * HD + gn] =
                        make_float2(C[t2][j][2 * hf], C[t2][j][2 * hf + 1]);
            }
}

__global__ __launch_bounds__(256) void out_tc(
    const float* __restrict__ Wo, const float* __restrict__ bo, float* __restrict__ out)
{
    extern __shared__ char smc[];
    u32 smb = smem_u32(smc);
    const int m0 = blockIdx.y * 128, n0 = blockIdx.x * 128;

    float C[2][8][4];
    #pragma unroll
    for (int a = 0; a < 2; a++)
        #pragma unroll
        for (int b = 0; b < 8; b++)
            #pragma unroll
            for (int q = 0; q < 4; q++) C[a][b][q] = 0.f;

    gemm_mma(C, g_ao, HD, BN, m0, Wo, DIMX, n0, HD, smc, smb);

    const int lane = threadIdx.x & 31, wid = threadIdx.x >> 5;
    const int wm = m0 + (wid >> 1) * 32, wn = n0 + (wid & 1) * 64;
    #pragma unroll
    for (int t2 = 0; t2 < 2; t2++)
        #pragma unroll
        for (int j = 0; j < 8; j++)
            #pragma unroll
            for (int hf = 0; hf < 2; hf++) {
                int gm = wm + 16 * t2 + (lane >> 2) + 8 * hf;
                int gn = wn + 8 * j + 2 * (lane & 3);
                float2 bv = *(const float2*)&bo[gn];
                *(float2*)&out[(size_t)gm * DIMX + gn] =
                    make_float2(C[t2][j][2 * hf] + bv.x, C[t2][j][2 * hf + 1] + bv.y);
            }
}

// ================= tensorized block-sparse attention =================
// smem layout (bytes); bf16 tiles use stride 72 elems (144B/row)
#define AT_QCH 0
#define AT_QCL 9216
#define AT_QRH 18432
#define AT_QRL 27648
#define AT_KH  36864
#define AT_KL  46080
#define AT_VH  55296
#define AT_VL  64512
#define AT_RBH 73728
#define AT_RBL 92160
#define AT_T   110592            // fp32 T[64][132]
#define ATTN_SMEM (110592 + 64 * 132 * 4)   // 144384

// convert fp32 pair -> write hi/lo bf16x2 words
__device__ __forceinline__ void st_pair(char* hb, char* lb, int off, float x, float y) {
    u32 lo; u32 hi = pack2(x, y, lo);
    *(u32*)(hb + off) = hi;
    *(u32*)(lb + off) = lo;
}

// A fragment m16k16, row-major src, stride 144B
__device__ __forceinline__ void ldA_frag(u32* A, u32 base, int row0, int kk, int lane) {
    u32 addr = base + (u32)((row0 + (lane & 15)) * 144 + (kk * 16 + ((lane >> 4) << 3)) * 2);
    ldsm4(A[0], A[1], A[2], A[3], addr);
}
// B fragments (two n8 frags), B = rows of row-major [n][k] tile (non-trans)
__device__ __forceinline__ void ldB_rows(u32* B4, u32 base, int nb, int kk, int lane) {
    int n = nb * 16 + (lane & 7) + ((lane >> 4) & 1) * 8;
    int ko = kk * 16 + ((lane >> 3) & 1) * 8;
    ldsm4(B4[0], B4[1], B4[2], B4[3], base + (u32)(n * 144 + ko * 2));
}
// B fragments for PV: V row-major [j][d], trans
__device__ __forceinline__ void ldB_vt(u32* B4, u32 base, int nb, int kk, int lane) {
    int kr = kk * 16 + (lane & 7) + ((lane >> 3) & 1) * 8;
    int nofs = nb * 16 + ((lane >> 4) & 1) * 8;
    ldsm4t(B4[0], B4[1], B4[2], B4[3], base + (u32)(kr * 144 + nofs * 2));
}

__global__ __launch_bounds__(128) void attn_kernel()
{
    extern __shared__ char smc[];
    u32 smb = smem_u32(smc);
    float* Tsm = (float*)(smc + AT_T);

    const int bh = blockIdx.x;
    const int qt = blockIdx.y;
    const int b  = bh >> 3, h = bh & 7;
    const int i0 = qt * 64;
    const int tid = threadIdx.x;
    const int lane = tid & 31, wid = tid >> 5;
    const int wm = wid * 16;
    const int i1 = wm + (lane >> 2), i2 = i1 + 8;     // local query rows owned
    const int cq = 2 * (lane & 3);                    // col offset within frag

    const float* qcg = g_qc + (size_t)(bh * NSEQ + i0) * DK;
    const float* qrg = g_qr + (size_t)(bh * NSEQ + i0) * DK;
    const float* kg  = g_k  + (size_t)bh * NSEQ * DK;
    const float* vg  = g_v  + (size_t)bh * NSEQ * DK;

    // ---- load Q tiles (fp32 -> hi/lo bf16) ----
    {
        int row = tid >> 1, dq = (tid & 1) * 32;
        const float* pc = qcg + row * 64 + dq;
        const float* pr = qrg + row * 64 + dq;
        #pragma unroll
        for (int i = 0; i < 8; i++) {
            float4 vc = *(const float4*)(pc + 4 * i);
            float4 vr = *(const float4*)(pr + 4 * i);
            int off = row * 144 + (dq + 4 * i) * 2;
            st_pair(smc + AT_QCH, smc + AT_QCL, off,     vc.x, vc.y);
            st_pair(smc + AT_QCH, smc + AT_QCL, off + 4, vc.z, vc.w);
            st_pair(smc + AT_QRH, smc + AT_QRL, off,     vr.x, vr.y);
            st_pair(smc + AT_QRH, smc + AT_QRL, off + 4, vr.z, vr.w);
        }
    }

    float m_i[2] = {-1e30f, -1e30f}, l_i[2] = {0.f, 0.f};
    float O[8][4];
    #pragma unroll
    for (int f = 0; f < 8; f++)
        #pragma unroll
        for (int e = 0; e < 4; e++) O[f][e] = 0.f;

    const int bi = qt >> 1;
    int lo, hi;
    if (bi == 0) { lo = 0; hi = 3; }
    else { lo = (bi - 1) * 2; hi = ((bi < 11) ? (bi + 1) : 11) * 2 + 1; }
    const bool do_mini = (lo > 0);
    const bool do_glob = (qt == 0);

    for (int t = lo; t <= hi; t++) {
        const int j0 = t * 64;
        __syncthreads();
        // ---- load K, V tiles ----
        {
            int row = tid >> 1, dq = (tid & 1) * 32;
            const float* pk = kg + (j0 + row) * 64 + dq;
            const float* pv = vg + (j0 + row) * 64 + dq;
            #pragma unroll
            for (int i = 0; i < 8; i++) {
                float4 vk = *(const float4*)(pk + 4 * i);
                float4 vv = *(const float4*)(pv + 4 * i);
                int off = row * 144 + (dq + 4 * i) * 2;
                st_pair(smc + AT_KH, smc + AT_KL, off,     vk.x, vk.y);
                st_pair(smc + AT_KH, smc + AT_KL, off + 4, vk.z, vk.w);
                st_pair(smc + AT_VH, smc + AT_VL, off,     vv.x, vv.y);
                st_pair(smc + AT_VH, smc + AT_VL, off + 4, vv.z, vv.w);
            }
        }
        // ---- load 127-row rel band (row 127 zeroed) ----
        {
            const int gbase = (j0 - i0) + 1472;
            if (tid < 127) {
                const float* pr = g_relk + (size_t)(gbase + tid) * HD + h * DK;
                #pragma unroll
                for (int i = 0; i < 16; i++) {
                    float4 v = *(const float4*)(pr + 4 * i);
                    int off = tid * 144 + (4 * i) * 2;
                    st_pair(smc + AT_RBH, smc + AT_RBL, off,     v.x, v.y);
                    st_pair(smc + AT_RBH, smc + AT_RBL, off + 4, v.z, v.w);
                }
            } else {
                #pragma unroll
                for (int i = 0; i < 16; i++) {
                    *(u64*)(smc + AT_RBH + 127 * 144 + 8 * i) = 0ull;
                    *(u64*)(smc + AT_RBL + 127 * 144 + 8 * i) = 0ull;
                }
            }
        }
        __syncthreads();

        // ---- S = Qc.K^T (bf16x3) ----
        float Sc[8][4];
        #pragma unroll
        for (int f = 0; f < 8; f++)
            #pragma unroll
            for (int e = 0; e < 4; e++) Sc[f][e] = 0.f;

        #pragma unroll
        for (int kk = 0; kk < 4; kk++) {
            u32 Ah[4], Al[4];
            ldA_frag(Ah, smb + AT_QCH, wm, kk, lane);
            ldA_frag(Al, smb + AT_QCL, wm, kk, lane);
            #pragma unroll
            for (int nb = 0; nb < 4; nb++) {
                u32 bhf[4], blf[4];
                ldB_rows(bhf, smb + AT_KH, nb, kk, lane);
                ldB_rows(blf, smb + AT_KL, nb, kk, lane);
                mma16816(Sc[2 * nb], Ah, bhf);     mma16816(Sc[2 * nb + 1], Ah, bhf + 2);
                mma16816(Sc[2 * nb], Ah, blf);     mma16816(Sc[2 * nb + 1], Ah, blf + 2);
                mma16816(Sc[2 * nb], Al, bhf);     mma16816(Sc[2 * nb + 1], Al, bhf + 2);
            }
        }

        // ---- T = Qr.RB^T in two halves, store to Tsm (warp-private rows) ----
        #pragma unroll
        for (int half = 0; half < 2; half++) {
            float Tr[8][4];
            #pragma unroll
            for (int f = 0; f < 8; f++)
                #pragma unroll
                for (int e = 0; e < 4; e++) Tr[f][e] = 0.f;
            #pragma unroll
            for (int kk = 0; kk < 4; kk++) {
                u32 Ah[4], Al[4];
                ldA_frag(Ah, smb + AT_QRH, wm, kk, lane);
                ldA_frag(Al, smb + AT_QRL, wm, kk, lane);
                #pragma unroll
                for (int nb = 0; nb < 4; nb++) {
                    int nbb = half * 4 + nb;
                    u32 bhf[4], blf[4];
                    ldB_rows(bhf, smb + AT_RBH, nbb, kk, lane);
                    ldB_rows(blf, smb + AT_RBL, nbb, kk, lane);
                    mma16816(Tr[2 * nb], Ah, bhf);     mma16816(Tr[2 * nb + 1], Ah, bhf + 2);
                    mma16816(Tr[2 * nb], Ah, blf);     mma16816(Tr[2 * nb + 1], Ah, blf + 2);
                    mma16816(Tr[2 * nb], Al, bhf);     mma16816(Tr[2 * nb + 1], Al, bhf + 2);
                }
            }
            #pragma unroll
            for (int f = 0; f < 8; f++) {
                int c = half * 64 + 8 * f + cq;
                *(float2*)&Tsm[i1 * 132 + c] = make_float2(Tr[f][0], Tr[f][1]);
                *(float2*)&Tsm[i2 * 132 + c] = make_float2(Tr[f][2], Tr[f][3]);
            }
        }
        __syncwarp();

        // ---- combine: S[i][j] += T[i][j-i+63] ----
        #pragma unroll
        for (int f = 0; f < 8; f++) {
            int jc = 8 * f + cq;
            Sc[f][0] += Tsm[i1 * 132 + jc - i1 + 63];
            Sc[f][1] += Tsm[i1 * 132 + jc - i1 + 64];
            Sc[f][2] += Tsm[i2 * 132 + jc - i2 + 63];
            Sc[f][3] += Tsm[i2 * 132 + jc - i2 + 64];
        }

        // ---- online softmax (rows i1, i2) ----
        float mx0 = -1e30f, mx1 = -1e30f;
        #pragma unroll
        for (int f = 0; f < 8; f++) {
            mx0 = fmaxf(mx0, fmaxf(Sc[f][0], Sc[f][1]));
            mx1 = fmaxf(mx1, fmaxf(Sc[f][2], Sc[f][3]));
        }
        mx0 = fmaxf(mx0, __shfl_xor_sync(0xffffffffu, mx0, 1));
        mx0 = fmaxf(mx0, __shfl_xor_sync(0xffffffffu, mx0, 2));
        mx1 = fmaxf(mx1, __shfl_xor_sync(0xffffffffu, mx1, 1));
        mx1 = fmaxf(mx1, __shfl_xor_sync(0xffffffffu, mx1, 2));
        float mn0 = fmaxf(m_i[0], mx0), mn1 = fmaxf(m_i[1], mx1);
        float s0 = 0.f, s1 = 0.f;
        #pragma unroll
        for (int f = 0; f < 8; f++) {
            Sc[f][0] = __expf(Sc[f][0] - mn0); s0 += Sc[f][0];
            Sc[f][1] = __expf(Sc[f][1] - mn0); s0 += Sc[f][1];
            Sc[f][2] = __expf(Sc[f][2] - mn1); s1 += Sc[f][2];
            Sc[f][3] = __expf(Sc[f][3] - mn1); s1 += Sc[f][3];
        }
        s0 += __shfl_xor_sync(0xffffffffu, s0, 1);
        s0 += __shfl_xor_sync(0xffffffffu, s0, 2);
        s1 += __shfl_xor_sync(0xffffffffu, s1, 1);
        s1 += __shfl_xor_sync(0xffffffffu, s1, 2);
        float c0 = __expf(m_i[0] - mn0), c1 = __expf(m_i[1] - mn1);
        l_i[0] = l_i[0] * c0 + s0;  m_i[0] = mn0;
        l_i[1] = l_i[1] * c1 + s1;  m_i[1] = mn1;
        #pragma unroll
        for (int f = 0; f < 8; f++) {
            O[f][0] *= c0; O[f][1] *= c0;
            O[f][2] *= c1; O[f][3] *= c1;
        }

        // ---- O += P.V (P packed in registers) ----
        #pragma unroll
        for (int kt = 0; kt < 4; kt++) {
            u32 Ph[4], Pl[4];
            Ph[0] = pack2(Sc[2 * kt][0],     Sc[2 * kt][1],     Pl[0]);
            Ph[1] = pack2(Sc[2 * kt][2],     Sc[2 * kt][3],     Pl[1]);
            Ph[2] = pack2(Sc[2 * kt + 1][0], Sc[2 * kt + 1][1], Pl[2]);
            Ph[3] = pack2(Sc[2 * kt + 1][2], Sc[2 * kt + 1][3], Pl[3]);
            #pragma unroll
            for (int nb = 0; nb < 4; nb++) {
                u32 vh[4], vl[4];
                ldB_vt(vh, smb + AT_VH, nb, kt, lane);
                ldB_vt(vl, smb + AT_VL, nb, kt, lane);
                mma16816(O[2 * nb], Ph, vh);     mma16816(O[2 * nb + 1], Ph, vh + 2);
                mma16816(O[2 * nb], Ph, vl);     mma16816(O[2 * nb + 1], Ph, vl + 2);
                mma16816(O[2 * nb], Pl, vh);     mma16816(O[2 * nb + 1], Pl, vh + 2);
            }
        }
    }

    // ---- mini-phase: global columns 0..3 (qt >= 4) ----
    if (do_mini) {
        const int ig1 = i0 + i1, ig2 = i0 + i2;
        const __nv_bfloat16* QCH = (const __nv_bfloat16*)(smc + AT_QCH);
        const __nv_bfloat16* QCL = (const __nv_bfloat16*)(smc + AT_QCL);
        const __nv_bfloat16* QRH = (const __nv_bfloat16*)(smc + AT_QRH);
        const __nv_bfloat16* QRL = (const __nv_bfloat16*)(smc + AT_QRL);
        float sA[4] = {0.f, 0.f, 0.f, 0.f}, sB[4] = {0.f, 0.f, 0.f, 0.f};
        const float* rl1 = g_relk + (size_t)(1535 - ig1) * HD + h * DK;
        const float* rl2 = g_relk + (size_t)(1535 - ig2) * HD + h * DK;
        for (int d = 0; d < 64; d++) {
            float qc1 = __bfloat162float(QCH[i1 * 72 + d]) + __bfloat162float(QCL[i1 * 72 + d]);
            float qr1 = __bfloat162float(QRH[i1 * 72 + d]) + __bfloat162float(QRL[i1 * 72 + d]);
            float qc2 = __bfloat162float(QCH[i2 * 72 + d]) + __bfloat162float(QCL[i2 * 72 + d]);
            float qr2 = __bfloat162float(QRH[i2 * 72 + d]) + __bfloat162float(QRL[i2 * 72 + d]);
            #pragma unroll
            for (int c = 0; c < 4; c++) {
                float kv = kg[c * 64 + d];
                sA[c] += qc1 * kv + qr1 * rl1[c * HD + d];
                sB[c] += qc2 * kv + qr2 * rl2[c * HD + d];
            }
        }
        // merge rows i1 (state 0) and i2 (state 1)
        {
            float mx = fmaxf(fmaxf(sA[0], sA[1]), fmaxf(sA[2], sA[3]));
            float mn = fmaxf(m_i[0], mx);
            float cr = __expf(m_i[0] - mn);
            float p[4], ps = 0.f;
            #pragma unroll
            for (int c = 0; c < 4; c++) { p[c] = __expf(sA[c] - mn); ps += p[c]; }
            l_i[0] = l_i[0] * cr + ps; m_i[0] = mn;
            #pragma unroll
            for (int f = 0; f < 8; f++)
                #pragma unroll
                for (int e = 0; e < 2; e++) {
                    int d = 8 * f + cq + e;
                    float acc = O[f][e] * cr;
                    #pragma unroll
                    for (int c = 0; c < 4; c++) acc += p[c] * vg[c * 64 + d];
                    O[f][e] = acc;
                }
        }
        {
            float mx = fmaxf(fmaxf(sB[0], sB[1]), fmaxf(sB[2], sB[3]));
            float mn = fmaxf(m_i[1], mx);
            float cr = __expf(m_i[1] - mn);
            float p[4], ps = 0.f;
            #pragma unroll
            for (int c = 0; c < 4; c++) { p[c] = __expf(sB[c] - mn); ps += p[c]; }
            l_i[1] = l_i[1] * cr + ps; m_i[1] = mn;
            #pragma unroll
            for (int f = 0; f < 8; f++)
                #pragma unroll
                for (int e = 0; e < 2; e++) {
                    int d = 8 * f + cq + e;
                    float acc = O[f][2 + e] * cr;
                    #pragma unroll
                    for (int c = 0; c < 4; c++) acc += p[c] * vg[c * 64 + d];
                    O[f][2 + e] = acc;
                }
        }
    }

    // ---- dense phase: qt==0, rows 0..3 x cols 256..1535 ----
    if (do_glob) {
        __syncthreads();
        float* Sx  = Tsm;              // 4 x 1280
        float* Qf  = Tsm + 5120;       // 8 x 64 (qc rows 0..3, qr rows 0..3)
        float* O2  = Qf + 512;         // 4 x 64
        float* ML  = O2 + 256;         // 8
        float* wst = ML + 8;           // 4 warps x 4

        {
            const __nv_bfloat16* QCH = (const __nv_bfloat16*)(smc + AT_QCH);
            const __nv_bfloat16* QCL = (const __nv_bfloat16*)(smc + AT_QCL);
            const __nv_bfloat16* QRH = (const __nv_bfloat16*)(smc + AT_QRH);
            const __nv_bfloat16* QRL = (const __nv_bfloat16*)(smc + AT_QRL);
            #pragma unroll
            for (int u = 0; u < 4; u++) {
                int idx = tid * 4 + u;
                int r = idx >> 6, d = idx & 63;
                float v;
                if (r < 4)
                    v = __bfloat162float(QCH[r * 72 + d]) + __bfloat162float(QCL[r * 72 + d]);
                else
                    v = __bfloat162float(QRH[(r - 4) * 72 + d]) + __bfloat162float(QRL[(r - 4) * 72 + d]);
                Qf[idx] = v;
            }
        }
        __syncthreads();

        float mloc[4] = {-1e30f, -1e30f, -1e30f, -1e30f};
        #pragma unroll
        for (int u = 0; u < 10; u++) {
            int jloc = u * 128 + tid;
            int j = 256 + jloc;
            const float* kr = kg + j * 64;
            const float* rl = g_relk + (size_t)(j + 1535) * HD + h * DK;
            float a0 = 0.f, a1 = 0.f, a2 = 0.f, a3 = 0.f;
            #pragma unroll 8
            for (int d = 0; d < 64; d++) {
                float kv = kr[d];
                a0 += Qf[d] * kv        + Qf[256 + d] * rl[d];
                a1 += Qf[64 + d] * kv   + Qf[320 + d] * rl[d - HD];
                a2 += Qf[128 + d] * kv  + Qf[384 + d] * rl[d - 2 * HD];
                a3 += Qf[192 + d] * kv  + Qf[448 + d] * rl[d - 3 * HD];
            }
            Sx[jloc] = a0; Sx[1280 + jloc] = a1;
            Sx[2560 + jloc] = a2; Sx[3840 + jloc] = a3;
            mloc[0] = fmaxf(mloc[0], a0); mloc[1] = fmaxf(mloc[1], a1);
            mloc[2] = fmaxf(mloc[2], a2); mloc[3] = fmaxf(mloc[3], a3);
        }
        #pragma unroll
        for (int r = 0; r < 4; r++)
            #pragma unroll
            for (int off = 16; off >= 1; off >>= 1)
                mloc[r] = fmaxf(mloc[r], __shfl_xor_sync(0xffffffffu, mloc[r], off));
        if (lane == 0)
            #pragma unroll
            for (int r = 0; r < 4; r++) wst[wid * 4 + r] = mloc[r];
        __syncthreads();
        if (tid < 4) {
            float m = -1e30f;
            #pragma unroll
            for (int w = 0; w < 4; w++) m = fmaxf(m, wst[w * 4 + tid]);
            ML[tid] = m;
        }
        __syncthreads();
        float M2r[4] = {ML[0], ML[1], ML[2], ML[3]};
        float lloc[4] = {0.f, 0.f, 0.f, 0.f};
        #pragma unroll
        for (int u = 0; u < 10; u++) {
            int jloc = u * 128 + tid;
            #pragma unroll
            for (int r = 0; r < 4; r++) {
                float p = __expf(Sx[r * 1280 + jloc] - M2r[r]);
                Sx[r * 1280 + jloc] = p;
                lloc[r] += p;
            }
        }
        #pragma unroll
        for (int r = 0; r < 4; r++)
            #pragma unroll
            for (int off = 16; off >= 1; off >>= 1)
                lloc[r] += __shfl_xor_sync(0xffffffffu, lloc[r], off);
        if (lane == 0)
            #pragma unroll
            for (int r = 0; r < 4; r++) wst[wid * 4 + r] = lloc[r];
        __syncthreads();
        if (tid < 4) {
            float s = 0.f;
            #pragma unroll
            for (int w = 0; w < 4; w++) s += wst[w * 4 + tid];
            ML[4 + tid] = s;
        }
        __syncthreads();

        #pragma unroll
        for (int u = 0; u < 2; u++) {
            int idx = u * 128 + tid;
            int r = idx >> 6, d = idx & 63;
            const float* vp = vg + 256 * 64 + d;
            const float* px = Sx + r * 1280;
            float o = 0.f;
            #pragma unroll 4
            for (int jj = 0; jj < 1280; jj++)
                o += px[jj] * vp[jj * 64];
            O2[r * 64 + d] = o;
        }
        __syncthreads();

        if (wid == 0 && (lane >> 2) < 4) {
            int r = lane >> 2;           // == i1, global row r (i0 == 0)
            float M2v = ML[r], L2v = ML[4 + r];
            float mn = fmaxf(m_i[0], M2v);
            float cA = __expf(m_i[0] - mn);
            float cB = __expf(M2v - mn);
            l_i[0] = l_i[0] * cA + L2v * cB;
            m_i[0] = mn;
            #pragma unroll
            for (int f = 0; f < 8; f++)
                #pragma unroll
                for (int e = 0; e < 2; e++) {
                    int d = 8 * f + cq + e;
                    O[f][e] = O[f][e] * cA + O2[r * 64 + d] * cB;
                }
        }
    }

    // ---- normalize + write ----
    {
        float inv0 = 1.f / l_i[0], inv1 = 1.f / l_i[1];
        float* o1 = &g_ao[(size_t)(b * NSEQ + i0 + i1) * HD + h * DK];
        float* o2 = &g_ao[(size_t)(b * NSEQ + i0 + i2) * HD + h * DK];
        #pragma unroll
        for (int f = 0; f < 8; f++) {
            int d = 8 * f + cq;
            *(float2*)&o1[d] = make_float2(O[f][0] * inv0, O[f][1] * inv0);
            *(float2*)&o2[d] = make_float2(O[f][2] * inv1, O[f][3] * inv1);
        }
    }
}

// ================= launch =================
extern "C" void kernel_launch(void* const* d_in, const int* in_sizes, int n_in,
                              void* d_out, int out_size)
{
    const float* x    = (const float*)d_in[0];
    const float* Wq   = (const float*)d_in[1];
    const float* Wk   = (const float*)d_in[2];
    const float* Wv   = (const float*)d_in[3];
    const float* Wrel = (const float*)d_in[4];
    const float* rcb  = (const float*)d_in[5];
    const float* rpb  = (const float*)d_in[6];
    const float* Wo   = (const float*)d_in[7];
    const float* bo   = (const float*)d_in[8];
    const float* pe   = (const float*)d_in[9];
    float* out = (float*)d_out;

    cudaFuncSetAttribute(attn_kernel, cudaFuncAttributeMaxDynamicSharedMemorySize, ATTN_SMEM);
    cudaFuncSetAttribute(qkv_tc,  cudaFuncAttributeMaxDynamicSharedMemorySize, GEMM_SMEM);
    cudaFuncSetAttribute(relk_tc, cudaFuncAttributeMaxDynamicSharedMemorySize, GEMM_SMEM);
    cudaFuncSetAttribute(out_tc,  cudaFuncAttributeMaxDynamicSharedMemorySize, GEMM_SMEM);

    qkv_tc <<<dim3(4, 24, 3), 256, GEMM_SMEM>>>(x, Wq, Wk, Wv, rcb, rpb);
    relk_tc<<<dim3(4, 24),    256, GEMM_SMEM>>>(pe, Wrel);
    attn_kernel<<<dim3(16, 24), 128, ATTN_SMEM>>>();
    out_tc <<<dim3(12, 24),   256, GEMM_SMEM>>>(Wo, bo, out);
}

// round 9
// speedup vs baseline: 2.7348x; 1.1235x over previous
#include <cuda_runtime.h>
#include <cuda_bf16.h>
#include <math.h>

#define BATCH 2
#define NSEQ 1536
#define DIMX 1536
#define HEADS 8
#define DK 64
#define HD 512
#define BN 3072
#define NPOS 3071
#define NRPFK 192

typedef unsigned long long u64;
typedef unsigned int u32;

__device__ __forceinline__ u32 smem_u32(const void* p) {
    u32 a;
    asm("{ .reg .u64 t; cvta.to.shared.u64 t, %1; cvt.u32.u64 %0, t; }" : "=r"(a) : "l"(p));
    return a;
}

// ================= warp MMA primitives =================
__device__ __forceinline__ void ldsm4(u32 &r0, u32 &r1, u32 &r2, u32 &r3, u32 addr) {
    asm volatile("ldmatrix.sync.aligned.m8n8.x4.shared.b16 {%0,%1,%2,%3}, [%4];"
                 : "=r"(r0), "=r"(r1), "=r"(r2), "=r"(r3) : "r"(addr));
}
__device__ __forceinline__ void ldsm4t(u32 &r0, u32 &r1, u32 &r2, u32 &r3, u32 addr) {
    asm volatile("ldmatrix.sync.aligned.m8n8.x4.trans.shared.b16 {%0,%1,%2,%3}, [%4];"
                 : "=r"(r0), "=r"(r1), "=r"(r2), "=r"(r3) : "r"(addr));
}
__device__ __forceinline__ void mma16816(float* d, const u32* a, const u32* b) {
    asm volatile("mma.sync.aligned.m16n8k16.row.col.f32.bf16.bf16.f32 "
        "{%0,%1,%2,%3}, {%4,%5,%6,%7}, {%8,%9}, {%0,%1,%2,%3};"
        : "+f"(d[0]), "+f"(d[1]), "+f"(d[2]), "+f"(d[3])
        : "r"(a[0]), "r"(a[1]), "r"(a[2]), "r"(a[3]), "r"(b[0]), "r"(b[1]));
}
__device__ __forceinline__ u32 pack2(float x, float y, u32 &lo) {
    __nv_bfloat16 hx = __float2bfloat16(x), hy = __float2bfloat16(y);
    __nv_bfloat16 lx = __float2bfloat16(x - __bfloat162float(hx));
    __nv_bfloat16 ly = __float2bfloat16(y - __bfloat162float(hy));
    lo = (u32)__bfloat16_as_ushort(lx) | ((u32)__bfloat16_as_ushort(ly) << 16);
    return (u32)__bfloat16_as_ushort(hx) | ((u32)__bfloat16_as_ushort(hy) << 16);
}

// ================= cp.async =================
#define CP16(dst, src) \
    asm volatile("cp.async.cg.shared.global [%0], [%1], 16;" :: "r"(dst), "l"(src) : "memory")
#define CP_COMMIT() asm volatile("cp.async.commit_group;" ::: "memory")
#define CP_WAIT0()  asm volatile("cp.async.wait_group 0;" ::: "memory")
#define CP_WAIT1()  asm volatile("cp.async.wait_group 1;" ::: "memory")

// ================= scratch =================
__device__ __align__(16) float g_k [16 * 1536 * 64];
__device__ __align__(16) float g_v [16 * 1536 * 64];
__device__ __align__(16) float g_relk[3071 * 512];
__device__ __align__(16) __nv_bfloat16 p_xh[3072 * 1536], p_xl[3072 * 1536];
__device__ __align__(16) __nv_bfloat16 p_w3h[3 * 1536 * 512], p_w3l[3 * 1536 * 512];
__device__ __align__(16) __nv_bfloat16 p_woh[512 * 1536], p_wol[512 * 1536];
__device__ __align__(16) __nv_bfloat16 p_peh[3071 * 192], p_pel[3071 * 192];
__device__ __align__(16) __nv_bfloat16 p_wrh[192 * 512], p_wrl[192 * 512];
__device__ __align__(16) u32 p_qch[16 * 1536 * 32], p_qcl[16 * 1536 * 32];
__device__ __align__(16) u32 p_qrh[16 * 1536 * 32], p_qrl[16 * 1536 * 32];
__device__ __align__(16) u32 p_kh [16 * 1536 * 32], p_kl [16 * 1536 * 32];
__device__ __align__(16) u32 p_vh [16 * 1536 * 32], p_vl [16 * 1536 * 32];
__device__ __align__(16) u32 p_rbh[3071 * 256], p_rbl[3071 * 256];
__device__ __align__(16) u32 p_aoh[3072 * 256], p_aol[3072 * 256];

// ================= pack kernel =================
__global__ void pack_hl(const float4* __restrict__ src, u64* __restrict__ dh,
                        u64* __restrict__ dl, int n4)
{
    int i = blockIdx.x * blockDim.x + threadIdx.x;
    if (i >= n4) return;
    float4 v = src[i];
    u32 l0, l1;
    u32 h0 = pack2(v.x, v.y, l0);
    u32 h1 = pack2(v.z, v.w, l1);
    dh[i] = (u64)h0 | ((u64)h1 << 32);
    dl[i] = (u64)l0 | ((u64)l1 << 32);
}

// ================= GEMM tiling =================
#define BK 32
#define SA_STRIDE 80
#define SA_BYTES (128 * SA_STRIDE)
#define SB_BYTES (BK * 256)
#define STAGE_BYTES (2 * SA_BYTES + 2 * SB_BYTES)
#define OFF_A_HI(s) ((s) * STAGE_BYTES)
#define OFF_A_LO(s) (OFF_A_HI(s) + SA_BYTES)
#define OFF_B_HI(s) (OFF_A_HI(s) + 2 * SA_BYTES)
#define OFF_B_LO(s) (OFF_B_HI(s) + SB_BYTES)
#define GEMM_SMEM (2 * STAGE_BYTES)

__device__ __forceinline__ void mma_chunk(float (&C)[2][8][4], int s, u32 smb)
{
    const int lane = threadIdx.x & 31, wid = threadIdx.x >> 5;
    const int wm = (wid >> 1) * 32, wn = (wid & 1) * 64;
    const u32 aoff[3] = { smb + (u32)OFF_A_HI(s), smb + (u32)OFF_A_HI(s), smb + (u32)OFF_A_LO(s) };
    const u32 boff[3] = { smb + (u32)OFF_B_HI(s), smb + (u32)OFF_B_LO(s), smb + (u32)OFF_B_HI(s) };

    #pragma unroll
    for (int ks = 0; ks < 2; ks++) {
        const int kb = ks * 16;
        #pragma unroll
        for (int p = 0; p < 3; p++) {
            u32 A0[4], A1[4], Bf[8][2];
            {
                int m = wm + (lane & 15);
                int kk = kb + 8 * (lane >> 4);
                ldsm4(A0[0], A0[1], A0[2], A0[3], aoff[p] + m * SA_STRIDE + kk * 2);
                ldsm4(A1[0], A1[1], A1[2], A1[3], aoff[p] + (m + 16) * SA_STRIDE + kk * 2);
            }
            {
                int krow = kb + ((lane >> 3) & 1) * 8 + (lane & 7);
                int nofs = ((lane >> 4) & 1) * 8;
                int kx = krow & 7;
                #pragma unroll
                for (int pr = 0; pr < 4; pr++) {
                    int n = wn + pr * 16 + nofs;
                    u32 addr = boff[p] + krow * 256 + (((n >> 3) ^ kx) << 4);
                    ldsm4t(Bf[2 * pr][0], Bf[2 * pr][1], Bf[2 * pr + 1][0], Bf[2 * pr + 1][1], addr);
                }
            }
            #pragma unroll
            for (int j = 0; j < 8; j++) {
                mma16816(C[0][j], A0, Bf[j]);
                mma16816(C[1][j], A1, Bf[j]);
            }
        }
    }
}

// prepacked-input mainloop
__device__ __forceinline__ void gemm_mma_pk(float (&C)[2][8][4],
    const __nv_bfloat16* __restrict__ Ah, const __nv_bfloat16* __restrict__ Al,
    int lda, int Mg, int m0,
    const __nv_bfloat16* __restrict__ Bh, const __nv_bfloat16* __restrict__ Bl,
    int ldb, int n0, int K, u32 smb)
{
    const int NC = K / BK;
    const int tid = threadIdx.x;

    auto load_async = [&](int s, int kc) {
        // A: 128 rows x 32 bf16 = 4 x 16B chunks per row, 2 planes
        #pragma unroll
        for (int rep = 0; rep < 2; rep++) {
            int v = tid + rep * 256;
            int row = v >> 2, part = v & 3;
            int sr = m0 + row; if (sr > Mg - 1) sr = Mg - 1;
            const char* sh = (const char*)(Ah + (size_t)sr * lda + kc * BK) + part * 16;
            const char* sl = (const char*)(Al + (size_t)sr * lda + kc * BK) + part * 16;
            u32 d = (u32)(row * SA_STRIDE + part * 16);
            CP16(smb + OFF_A_HI(s) + d, sh);
            CP16(smb + OFF_A_LO(s) + d, sl);
        }
        // B: 32 rows x 128 bf16 = 16 x 16B chunks per row (FIX: both halves)
        {
            int k = tid >> 3, g = tid & 7;
            int kx = k & 7;
            const char* rh = (const char*)(Bh + (size_t)(kc * BK + k) * ldb + n0);
            const char* rl = (const char*)(Bl + (size_t)(kc * BK + k) * ldb + n0);
            #pragma unroll
            for (int hf = 0; hf < 2; hf++) {
                int gg = g + hf * 8;
                u32 d = (u32)(k * 256 + ((gg ^ kx) << 4));
                CP16(smb + OFF_B_HI(s) + d, rh + gg * 16);
                CP16(smb + OFF_B_LO(s) + d, rl + gg * 16);
            }
        }
        CP_COMMIT();
    };

    load_async(0, 0);
    for (int c = 0; c < NC; c++) {
        int s = c & 1;
        if (c + 1 < NC) { load_async(s ^ 1, c + 1); CP_WAIT1(); }
        else            { CP_WAIT0(); }
        __syncthreads();
        mma_chunk(C, s, smb);
        __syncthreads();
    }
}

// ================= GEMM kernels =================
__global__ __launch_bounds__(256) void qkv_tc(
    const float* __restrict__ rcb, const float* __restrict__ rpb)
{
    extern __shared__ char smc[];
    u32 smb = smem_u32(smc);
    const int z = blockIdx.z;
    const int m0 = blockIdx.y * 128, n0 = blockIdx.x * 128;

    float C[2][8][4];
    #pragma unroll
    for (int a = 0; a < 2; a++)
        #pragma unroll
        for (int b = 0; b < 8; b++)
            #pragma unroll
            for (int q = 0; q < 4; q++) C[a][b][q] = 0.f;

    gemm_mma_pk(C, p_xh, p_xl, DIMX, BN, m0,
                p_w3h + (size_t)z * DIMX * HD, p_w3l + (size_t)z * DIMX * HD,
                HD, n0, DIMX, smb);

    const int lane = threadIdx.x & 31, wid = threadIdx.x >> 5;
    const int wm = m0 + (wid >> 1) * 32, wn = n0 + (wid & 1) * 64;
    #pragma unroll
    for (int t2 = 0; t2 < 2; t2++)
        #pragma unroll
        for (int j = 0; j < 8; j++)
            #pragma unroll
            for (int hf = 0; hf < 2; hf++) {
                int gm = wm + 16 * t2 + (lane >> 2) + 8 * hf;
                int gn = wn + 8 * j + 2 * (lane & 3);
                float v0 = C[t2][j][2 * hf], v1 = C[t2][j][2 * hf + 1];
                int bb = gm / NSEQ, ii = gm - bb * NSEQ;
                int hh = gn >> 6, dd = gn & 63;
                size_t i32 = ((size_t)(bb * HEADS + hh) * NSEQ + ii) * 32 + (dd >> 1);
                if (z == 0) {
                    float2 cb = *(const float2*)&rcb[gn];
                    float2 pb = *(const float2*)&rpb[gn];
                    u32 lo, hi;
                    hi = pack2(v0 * 0.125f + cb.x, v1 * 0.125f + cb.y, lo);
                    p_qch[i32] = hi; p_qcl[i32] = lo;
                    hi = pack2(v0 * 0.125f + pb.x, v1 * 0.125f + pb.y, lo);
                    p_qrh[i32] = hi; p_qrl[i32] = lo;
                } else {
                    size_t idx = ((size_t)(bb * HEADS + hh) * NSEQ + ii) * DK + dd;
                    u32 lo, hi = pack2(v0, v1, lo);
                    if (z == 1) {
                        *(float2*)&g_k[idx] = make_float2(v0, v1);
                        p_kh[i32] = hi; p_kl[i32] = lo;
                    } else {
                        *(float2*)&g_v[idx] = make_float2(v0, v1);
                        p_vh[i32] = hi; p_vl[i32] = lo;
                    }
                }
            }
}

__global__ __launch_bounds__(256) void relk_tc()
{
    extern __shared__ char smc[];
    u32 smb = smem_u32(smc);
    const int m0 = blockIdx.y * 128, n0 = blockIdx.x * 128;

    float C[2][8][4];
    #pragma unroll
    for (int a = 0; a < 2; a++)
        #pragma unroll
        for (int b = 0; b < 8; b++)
            #pragma unroll
            for (int q = 0; q < 4; q++) C[a][b][q] = 0.f;

    gemm_mma_pk(C, p_peh, p_pel, NRPFK, NPOS, m0, p_wrh, p_wrl, HD, n0, NRPFK, smb);

    const int lane = threadIdx.x & 31, wid = threadIdx.x >> 5;
    const int wm = m0 + (wid >> 1) * 32, wn = n0 + (wid & 1) * 64;
    #pragma unroll
    for (int t2 = 0; t2 < 2; t2++)
        #pragma unroll
        for (int j = 0; j < 8; j++)
            #pragma unroll
            for (int hf = 0; hf < 2; hf++) {
                int gm = wm + 16 * t2 + (lane >> 2) + 8 * hf;
                int gn = wn + 8 * j + 2 * (lane & 3);
                if (gm < NPOS) {
                    float v0 = C[t2][j][2 * hf], v1 = C[t2][j][2 * hf + 1];
                    *(float2*)&g_relk[(size_t)gm * HD + gn] = make_float2(v0, v1);
                    u32 lo, hi = pack2(v0, v1, lo);
                    size_t i32 = (size_t)gm * 256 + (gn >> 1);
                    p_rbh[i32] = hi; p_rbl[i32] = lo;
                }
            }
}

__global__ __launch_bounds__(256) void out_tc(
    const float* __restrict__ bo, float* __restrict__ out)
{
    extern __shared__ char smc[];
    u32 smb = smem_u32(smc);
    const int m0 = blockIdx.y * 128, n0 = blockIdx.x * 128;

    float C[2][8][4];
    #pragma unroll
    for (int a = 0; a < 2; a++)
        #pragma unroll
        for (int b = 0; b < 8; b++)
            #pragma unroll
            for (int q = 0; q < 4; q++) C[a][b][q] = 0.f;

    gemm_mma_pk(C, (const __nv_bfloat16*)p_aoh, (const __nv_bfloat16*)p_aol, HD, BN, m0,
                p_woh, p_wol, DIMX, n0, HD, smb);

    const int lane = threadIdx.x & 31, wid = threadIdx.x >> 5;
    const int wm = m0 + (wid >> 1) * 32, wn = n0 + (wid & 1) * 64;
    #pragma unroll
    for (int t2 = 0; t2 < 2; t2++)
        #pragma unroll
        for (int j = 0; j < 8; j++)
            #pragma unroll
            for (int hf = 0; hf < 2; hf++) {
                int gm = wm + 16 * t2 + (lane >> 2) + 8 * hf;
                int gn = wn + 8 * j + 2 * (lane & 3);
                float2 bv = *(const float2*)&bo[gn];
                *(float2*)&out[(size_t)gm * DIMX + gn] =
                    make_float2(C[t2][j][2 * hf] + bv.x, C[t2][j][2 * hf + 1] + bv.y);
            }
}

// ================= tensorized block-sparse attention =================
#define AT_QCH 0
#define AT_QCL 9216
#define AT_QRH 18432
#define AT_QRL 27648
#define AT_KH  36864
#define AT_KL  46080
#define AT_VH  55296
#define AT_VL  64512
#define AT_RBH 73728
#define AT_RBL 92160
#define AT_T   110592
#define ATTN_SMEM (110592 + 64 * 132 * 4)

__device__ __forceinline__ void ldA_frag(u32* A, u32 base, int row0, int kk, int lane) {
    u32 addr = base + (u32)((row0 + (lane & 15)) * 144 + (kk * 16 + ((lane >> 4) << 3)) * 2);
    ldsm4(A[0], A[1], A[2], A[3], addr);
}
__device__ __forceinline__ void ldB_rows(u32* B4, u32 base, int nb, int kk, int lane) {
    int n = nb * 16 + (lane & 7) + ((lane >> 4) & 1) * 8;
    int ko = kk * 16 + ((lane >> 3) & 1) * 8;
    ldsm4(B4[0], B4[1], B4[2], B4[3], base + (u32)(n * 144 + ko * 2));
}
__device__ __forceinline__ void ldB_vt(u32* B4, u32 base, int nb, int kk, int lane) {
    int kr = kk * 16 + (lane & 7) + ((lane >> 3) & 1) * 8;
    int nofs = nb * 16 + ((lane >> 4) & 1) * 8;
    ldsm4t(B4[0], B4[1], B4[2], B4[3], base + (u32)(kr * 144 + nofs * 2));
}

__global__ __launch_bounds__(128) void attn_kernel()
{
    extern __shared__ char smc[];
    u32 smb = smem_u32(smc);
    float* Tsm = (float*)(smc + AT_T);

    const int bh = blockIdx.x;
    const int qt = blockIdx.y;
    const int b  = bh >> 3, h = bh & 7;
    const int i0 = qt * 64;
    const int tid = threadIdx.x;
    const int lane = tid & 31, wid = tid >> 5;
    const int wm = wid * 16;
    const int i1 = wm + (lane >> 2), i2 = i1 + 8;
    const int cq = 2 * (lane & 3);

    const float* kg  = g_k + (size_t)bh * NSEQ * DK;
    const float* vg  = g_v + (size_t)bh * NSEQ * DK;

    // ---- load Q tiles ----
    {
        int row = tid >> 1, jo = (tid & 1) * 16;
        size_t gq = (size_t)(bh * NSEQ + i0 + row) * 32 + jo;
        const uint4* sq0 = (const uint4*)(p_qch + gq);
        const uint4* sq1 = (const uint4*)(p_qcl + gq);
        const uint4* sq2 = (const uint4*)(p_qrh + gq);
        const uint4* sq3 = (const uint4*)(p_qrl + gq);
        uint4* d0 = (uint4*)(smc + AT_QCH + row * 144 + jo * 4);
        uint4* d1 = (uint4*)(smc + AT_QCL + row * 144 + jo * 4);
        uint4* d2 = (uint4*)(smc + AT_QRH + row * 144 + jo * 4);
        uint4* d3 = (uint4*)(smc + AT_QRL + row * 144 + jo * 4);
        #pragma unroll
        for (int i = 0; i < 4; i++) {
            d0[i] = sq0[i]; d1[i] = sq1[i]; d2[i] = sq2[i]; d3[i] = sq3[i];
        }
    }

    float m_i[2] = {-1e30f, -1e30f}, l_i[2] = {0.f, 0.f};
    float O[8][4];
    #pragma unroll
    for (int f = 0; f < 8; f++)
        #pragma unroll
        for (int e = 0; e < 4; e++) O[f][e] = 0.f;

    const int bi = qt >> 1;
    int lo, hi;
    if (bi == 0) { lo = 0; hi = 3; }
    else { lo = (bi - 1) * 2; hi = ((bi < 11) ? (bi + 1) : 11) * 2 + 1; }
    const bool do_mini = (lo > 0);
    const bool do_glob = (qt == 0);

    for (int t = lo; t <= hi; t++) {
        const int j0 = t * 64;
        __syncthreads();
        {
            int row = tid >> 1, jo = (tid & 1) * 16;
            size_t gk = (size_t)(bh * NSEQ + j0 + row) * 32 + jo;
            const uint4* s0 = (const uint4*)(p_kh + gk);
            const uint4* s1 = (const uint4*)(p_kl + gk);
            const uint4* s2 = (const uint4*)(p_vh + gk);
            const uint4* s3 = (const uint4*)(p_vl + gk);
            uint4* d0 = (uint4*)(smc + AT_KH + row * 144 + jo * 4);
            uint4* d1 = (uint4*)(smc + AT_KL + row * 144 + jo * 4);
            uint4* d2 = (uint4*)(smc + AT_VH + row * 144 + jo * 4);
            uint4* d3 = (uint4*)(smc + AT_VL + row * 144 + jo * 4);
            #pragma unroll
            for (int i = 0; i < 4; i++) {
                d0[i] = s0[i]; d1[i] = s1[i]; d2[i] = s2[i]; d3[i] = s3[i];
            }
        }
        {
            const int gbase = (j0 - i0) + 1472;
            if (tid < 127) {
                size_t gb = (size_t)(gbase + tid) * 256 + h * 32;
                const uint4* sh = (const uint4*)(p_rbh + gb);
                const uint4* sl = (const uint4*)(p_rbl + gb);
                uint4* dh = (uint4*)(smc + AT_RBH + tid * 144);
                uint4* dl = (uint4*)(smc + AT_RBL + tid * 144);
                #pragma unroll
                for (int i = 0; i < 8; i++) { dh[i] = sh[i]; dl[i] = sl[i]; }
            } else if (tid == 127) {
                uint4 z = make_uint4(0, 0, 0, 0);
                uint4* dh = (uint4*)(smc + AT_RBH + 127 * 144);
                uint4* dl = (uint4*)(smc + AT_RBL + 127 * 144);
                #pragma unroll
                for (int i = 0; i < 8; i++) { dh[i] = z; dl[i] = z; }
            }
        }
        __syncthreads();

        float Sc[8][4];
        #pragma unroll
        for (int f = 0; f < 8; f++)
            #pragma unroll
            for (int e = 0; e < 4; e++) Sc[f][e] = 0.f;

        #pragma unroll
        for (int kk = 0; kk < 4; kk++) {
            u32 Ah[4], Al[4];
            ldA_frag(Ah, smb + AT_QCH, wm, kk, lane);
            ldA_frag(Al, smb + AT_QCL, wm, kk, lane);
            #pragma unroll
            for (int nb = 0; nb < 4; nb++) {
                u32 bhf[4], blf[4];
                ldB_rows(bhf, smb + AT_KH, nb, kk, lane);
                ldB_rows(blf, smb + AT_KL, nb, kk, lane);
                mma16816(Sc[2 * nb], Ah, bhf);     mma16816(Sc[2 * nb + 1], Ah, bhf + 2);
                mma16816(Sc[2 * nb], Ah, blf);     mma16816(Sc[2 * nb + 1], Ah, blf + 2);
                mma16816(Sc[2 * nb], Al, bhf);     mma16816(Sc[2 * nb + 1], Al, bhf + 2);
            }
        }

        #pragma unroll
        for (int half = 0; half < 2; half++) {
            float Tr[8][4];
            #pragma unroll
            for (int f = 0; f < 8; f++)
                #pragma unroll
                for (int e = 0; e < 4; e++) Tr[f][e] = 0.f;
            #pragma unroll
            for (int kk = 0; kk < 4; kk++) {
                u32 Ah[4], Al[4];
                ldA_frag(Ah, smb + AT_QRH, wm, kk, lane);
                ldA_frag(Al, smb + AT_QRL, wm, kk, lane);
                #pragma unroll
                for (int nb = 0; nb < 4; nb++) {
                    int nbb = half * 4 + nb;
                    u32 bhf[4], blf[4];
                    ldB_rows(bhf, smb + AT_RBH, nbb, kk, lane);
                    ldB_rows(blf, smb + AT_RBL, nbb, kk, lane);
                    mma16816(Tr[2 * nb], Ah, bhf);     mma16816(Tr[2 * nb + 1], Ah, bhf + 2);
                    mma16816(Tr[2 * nb], Ah, blf);     mma16816(Tr[2 * nb + 1], Ah, blf + 2);
                    mma16816(Tr[2 * nb], Al, bhf);     mma16816(Tr[2 * nb + 1], Al, bhf + 2);
                }
            }
            #pragma unroll
            for (int f = 0; f < 8; f++) {
                int c = half * 64 + 8 * f + cq;
                *(float2*)&Tsm[i1 * 132 + c] = make_float2(Tr[f][0], Tr[f][1]);
                *(float2*)&Tsm[i2 * 132 + c] = make_float2(Tr[f][2], Tr[f][3]);
            }
        }
        __syncwarp();

        #pragma unroll
        for (int f = 0; f < 8; f++) {
            int jc = 8 * f + cq;
            Sc[f][0] += Tsm[i1 * 132 + jc - i1 + 63];
            Sc[f][1] += Tsm[i1 * 132 + jc - i1 + 64];
            Sc[f][2] += Tsm[i2 * 132 + jc - i2 + 63];
            Sc[f][3] += Tsm[i2 * 132 + jc - i2 + 64];
        }

        float mx0 = -1e30f, mx1 = -1e30f;
        #pragma unroll
        for (int f = 0; f < 8; f++) {
            mx0 = fmaxf(mx0, fmaxf(Sc[f][0], Sc[f][1]));
            mx1 = fmaxf(mx1, fmaxf(Sc[f][2], Sc[f][3]));
        }
        mx0 = fmaxf(mx0, __shfl_xor_sync(0xffffffffu, mx0, 1));
        mx0 = fmaxf(mx0, __shfl_xor_sync(0xffffffffu, mx0, 2));
        mx1 = fmaxf(mx1, __shfl_xor_sync(0xffffffffu, mx1, 1));
        mx1 = fmaxf(mx1, __shfl_xor_sync(0xffffffffu, mx1, 2));
        float mn0 = fmaxf(m_i[0], mx0), mn1 = fmaxf(m_i[1], mx1);
        float s0 = 0.f, s1 = 0.f;
        #pragma unroll
        for (int f = 0; f < 8; f++) {
            Sc[f][0] = __expf(Sc[f][0] - mn0); s0 += Sc[f][0];
            Sc[f][1] = __expf(Sc[f][1] - mn0); s0 += Sc[f][1];
            Sc[f][2] = __expf(Sc[f][2] - mn1); s1 += Sc[f][2];
            Sc[f][3] = __expf(Sc[f][3] - mn1); s1 += Sc[f][3];
        }
        s0 += __shfl_xor_sync(0xffffffffu, s0, 1);
        s0 += __shfl_xor_sync(0xffffffffu, s0, 2);
        s1 += __shfl_xor_sync(0xffffffffu, s1, 1);
        s1 += __shfl_xor_sync(0xffffffffu, s1, 2);
        float c0 = __expf(m_i[0] - mn0), c1 = __expf(m_i[1] - mn1);
        l_i[0] = l_i[0] * c0 + s0;  m_i[0] = mn0;
        l_i[1] = l_i[1] * c1 + s1;  m_i[1] = mn1;
        #pragma unroll
        for (int f = 0; f < 8; f++) {
            O[f][0] *= c0; O[f][1] *= c0;
            O[f][2] *= c1; O[f][3] *= c1;
        }

        #pragma unroll
        for (int kt = 0; kt < 4; kt++) {
            u32 Ph[4], Pl[4];
            Ph[0] = pack2(Sc[2 * kt][0],     Sc[2 * kt][1],     Pl[0]);
            Ph[1] = pack2(Sc[2 * kt][2],     Sc[2 * kt][3],     Pl[1]);
            Ph[2] = pack2(Sc[2 * kt + 1][0], Sc[2 * kt + 1][1], Pl[2]);
            Ph[3] = pack2(Sc[2 * kt + 1][2], Sc[2 * kt + 1][3], Pl[3]);
            #pragma unroll
            for (int nb = 0; nb < 4; nb++) {
                u32 vh[4], vl[4];
                ldB_vt(vh, smb + AT_VH, nb, kt, lane);
                ldB_vt(vl, smb + AT_VL, nb, kt, lane);
                mma16816(O[2 * nb], Ph, vh);     mma16816(O[2 * nb + 1], Ph, vh + 2);
                mma16816(O[2 * nb], Ph, vl);     mma16816(O[2 * nb + 1], Ph, vl + 2);
                mma16816(O[2 * nb], Pl, vh);     mma16816(O[2 * nb + 1], Pl, vh + 2);
            }
        }
    }

    // ---- mini-phase ----
    if (do_mini) {
        const int ig1 = i0 + i1, ig2 = i0 + i2;
        const __nv_bfloat16* QCH = (const __nv_bfloat16*)(smc + AT_QCH);
        const __nv_bfloat16* QCL = (const __nv_bfloat16*)(smc + AT_QCL);
        const __nv_bfloat16* QRH = (const __nv_bfloat16*)(smc + AT_QRH);
        const __nv_bfloat16* QRL = (const __nv_bfloat16*)(smc + AT_QRL);
        float sA[4] = {0.f, 0.f, 0.f, 0.f}, sB[4] = {0.f, 0.f, 0.f, 0.f};
        const float* rl1 = g_relk + (size_t)(1535 - ig1) * HD + h * DK;
        const float* rl2 = g_relk + (size_t)(1535 - ig2) * HD + h * DK;
        for (int d = 0; d < 64; d++) {
            float qc1 = __bfloat162float(QCH[i1 * 72 + d]) + __bfloat162float(QCL[i1 * 72 + d]);
            float qr1 = __bfloat162float(QRH[i1 * 72 + d]) + __bfloat162float(QRL[i1 * 72 + d]);
            float qc2 = __bfloat162float(QCH[i2 * 72 + d]) + __bfloat162float(QCL[i2 * 72 + d]);
            float qr2 = __bfloat162float(QRH[i2 * 72 + d]) + __bfloat162float(QRL[i2 * 72 + d]);
            #pragma unroll
            for (int c = 0; c < 4; c++) {
                float kv = kg[c * 64 + d];
                sA[c] += qc1 * kv + qr1 * rl1[c * HD + d];
                sB[c] += qc2 * kv + qr2 * rl2[c * HD + d];
            }
        }
        {
            float mx = fmaxf(fmaxf(sA[0], sA[1]), fmaxf(sA[2], sA[3]));
            float mn = fmaxf(m_i[0], mx);
            float cr = __expf(m_i[0] - mn);
            float p[4], ps = 0.f;
            #pragma unroll
            for (int c = 0; c < 4; c++) { p[c] = __expf(sA[c] - mn); ps += p[c]; }
            l_i[0] = l_i[0] * cr + ps; m_i[0] = mn;
            #pragma unroll
            for (int f = 0; f < 8; f++)
                #pragma unroll
                for (int e = 0; e < 2; e++) {
                    int d = 8 * f + cq + e;
                    float acc = O[f][e] * cr;
                    #pragma unroll
                    for (int c = 0; c < 4; c++) acc += p[c] * vg[c * 64 + d];
                    O[f][e] = acc;
                }
        }
        {
            float mx = fmaxf(fmaxf(sB[0], sB[1]), fmaxf(sB[2], sB[3]));
            float mn = fmaxf(m_i[1], mx);
            float cr = __expf(m_i[1] - mn);
            float p[4], ps = 0.f;
            #pragma unroll
            for (int c = 0; c < 4; c++) { p[c] = __expf(sB[c] - mn); ps += p[c]; }
            l_i[1] = l_i[1] * cr + ps; m_i[1] = mn;
            #pragma unroll
            for (int f = 0; f < 8; f++)
                #pragma unroll
                for (int e = 0; e < 2; e++) {
                    int d = 8 * f + cq + e;
                    float acc = O[f][2 + e] * cr;
                    #pragma unroll
                    for (int c = 0; c < 4; c++) acc += p[c] * vg[c * 64 + d];
                    O[f][2 + e] = acc;
                }
        }
    }

    // ---- dense phase (qt==0) ----
    if (do_glob) {
        __syncthreads();
        float* Sx  = Tsm;
        float* Qf  = Tsm + 5120;
        float* O2  = Qf + 512;
        float* ML  = O2 + 256;
        float* wst = ML + 8;

        {
            const __nv_bfloat16* QCH = (const __nv_bfloat16*)(smc + AT_QCH);
            const __nv_bfloat16* QCL = (const __nv_bfloat16*)(smc + AT_QCL);
            const __nv_bfloat16* QRH = (const __nv_bfloat16*)(smc + AT_QRH);
            const __nv_bfloat16* QRL = (const __nv_bfloat16*)(smc + AT_QRL);
            #pragma unroll
            for (int u = 0; u < 4; u++) {
                int idx = tid * 4 + u;
                int r = idx >> 6, d = idx & 63;
                float v;
                if (r < 4)
                    v = __bfloat162float(QCH[r * 72 + d]) + __bfloat162float(QCL[r * 72 + d]);
                else
                    v = __bfloat162float(QRH[(r - 4) * 72 + d]) + __bfloat162float(QRL[(r - 4) * 72 + d]);
                Qf[idx] = v;
            }
        }
        __syncthreads();

        float mloc[4] = {-1e30f, -1e30f, -1e30f, -1e30f};
        #pragma unroll
        for (int u = 0; u < 10; u++) {
            int jloc = u * 128 + tid;
            int j = 256 + jloc;
            const float* kr = kg + j * 64;
            const float* rl = g_relk + (size_t)(j + 1535) * HD + h * DK;
            float a0 = 0.f, a1 = 0.f, a2 = 0.f, a3 = 0.f;
            #pragma unroll 8
            for (int d = 0; d < 64; d++) {
                float kv = kr[d];
                a0 += Qf[d] * kv        + Qf[256 + d] * rl[d];
                a1 += Qf[64 + d] * kv   + Qf[320 + d] * rl[d - HD];
                a2 += Qf[128 + d] * kv  + Qf[384 + d] * rl[d - 2 * HD];
                a3 += Qf[192 + d] * kv  + Qf[448 + d] * rl[d - 3 * HD];
            }
            Sx[jloc] = a0; Sx[1280 + jloc] = a1;
            Sx[2560 + jloc] = a2; Sx[3840 + jloc] = a3;
            mloc[0] = fmaxf(mloc[0], a0); mloc[1] = fmaxf(mloc[1], a1);
            mloc[2] = fmaxf(mloc[2], a2); mloc[3] = fmaxf(mloc[3], a3);
        }
        #pragma unroll
        for (int r = 0; r < 4; r++)
            #pragma unroll
            for (int off = 16; off >= 1; off >>= 1)
                mloc[r] = fmaxf(mloc[r], __shfl_xor_sync(0xffffffffu, mloc[r], off));
        if (lane == 0)
            #pragma unroll
            for (int r = 0; r < 4; r++) wst[wid * 4 + r] = mloc[r];
        __syncthreads();
        if (tid < 4) {
            float m = -1e30f;
            #pragma unroll
            for (int w = 0; w < 4; w++) m = fmaxf(m, wst[w * 4 + tid]);
            ML[tid] = m;
        }
        __syncthreads();
        float M2r[4] = {ML[0], ML[1], ML[2], ML[3]};
        float lloc[4] = {0.f, 0.f, 0.f, 0.f};
        #pragma unroll
        for (int u = 0; u < 10; u++) {
            int jloc = u * 128 + tid;
            #pragma unroll
            for (int r = 0; r < 4; r++) {
                float p = __expf(Sx[r * 1280 + jloc] - M2r[r]);
                Sx[r * 1280 + jloc] = p;
                lloc[r] += p;
            }
        }
        #pragma unroll
        for (int r = 0; r < 4; r++)
            #pragma unroll
            for (int off = 16; off >= 1; off >>= 1)
                lloc[r] += __shfl_xor_sync(0xffffffffu, lloc[r], off);
        if (lane == 0)
            #pragma unroll
            for (int r = 0; r < 4; r++) wst[wid * 4 + r] = lloc[r];
        __syncthreads();
        if (tid < 4) {
            float s = 0.f;
            #pragma unroll
            for (int w = 0; w < 4; w++) s += wst[w * 4 + tid];
            ML[4 + tid] = s;
        }
        __syncthreads();

        #pragma unroll
        for (int u = 0; u < 2; u++) {
            int idx = u * 128 + tid;
            int r = idx >> 6, d = idx & 63;
            const float* vp = vg + 256 * 64 + d;
            const float* px = Sx + r * 1280;
            float o = 0.f;
            #pragma unroll 4
            for (int jj = 0; jj < 1280; jj++)
                o += px[jj] * vp[jj * 64];
            O2[r * 64 + d] = o;
        }
        __syncthreads();

        if (wid == 0 && (lane >> 2) < 4) {
            int r = lane >> 2;
            float M2v = ML[r], L2v = ML[4 + r];
            float mn = fmaxf(m_i[0], M2v);
            float cA = __expf(m_i[0] - mn);
            float cB = __expf(M2v - mn);
            l_i[0] = l_i[0] * cA + L2v * cB;
            m_i[0] = mn;
            #pragma unroll
            for (int f = 0; f < 8; f++)
                #pragma unroll
                for (int e = 0; e < 2; e++) {
                    int d = 8 * f + cq + e;
                    O[f][e] = O[f][e] * cA + O2[r * 64 + d] * cB;
                }
        }
    }

    // ---- normalize + write packed ao ----
    {
        float inv0 = 1.f / l_i[0], inv1 = 1.f / l_i[1];
        size_t o1 = (size_t)(b * NSEQ + i0 + i1) * 256 + h * 32;
        size_t o2 = (size_t)(b * NSEQ + i0 + i2) * 256 + h * 32;
        #pragma unroll
        for (int f = 0; f < 8; f++) {
            int j = (8 * f + cq) >> 1;
            u32 lo, hi;
            hi = pack2(O[f][0] * inv0, O[f][1] * inv0, lo);
            p_aoh[o1 + j] = hi; p_aol[o1 + j] = lo;
            hi = pack2(O[f][2] * inv1, O[f][3] * inv1, lo);
            p_aoh[o2 + j] = hi; p_aol[o2 + j] = lo;
        }
    }
}

// ================= launch =================
extern "C" void kernel_launch(void* const* d_in, const int* in_sizes, int n_in,
                              void* d_out, int out_size)
{
    const float* x    = (const float*)d_in[0];
    const float* Wq   = (const float*)d_in[1];
    const float* Wk   = (const float*)d_in[2];
    const float* Wv   = (const float*)d_in[3];
    const float* Wrel = (const float*)d_in[4];
    const float* rcb  = (const float*)d_in[5];
    const float* rpb  = (const float*)d_in[6];
    const float* Wo   = (const float*)d_in[7];
    const float* bo   = (const float*)d_in[8];
    const float* pe   = (const float*)d_in[9];
    float* out = (float*)d_out;

    cudaFuncSetAttribute(attn_kernel, cudaFuncAttributeMaxDynamicSharedMemorySize, ATTN_SMEM);
    cudaFuncSetAttribute(qkv_tc,  cudaFuncAttributeMaxDynamicSharedMemorySize, GEMM_SMEM);
    cudaFuncSetAttribute(relk_tc, cudaFuncAttributeMaxDynamicSharedMemorySize, GEMM_SMEM);
    cudaFuncSetAttribute(out_tc,  cudaFuncAttributeMaxDynamicSharedMemorySize, GEMM_SMEM);

    void *xh, *xl, *w3h, *w3l, *woh, *wol, *peh, *pel, *wrh, *wrl;
    cudaGetSymbolAddress(&xh,  p_xh);  cudaGetSymbolAddress(&xl,  p_xl);
    cudaGetSymbolAddress(&w3h, p_w3h); cudaGetSymbolAddress(&w3l, p_w3l);
    cudaGetSymbolAddress(&woh, p_woh); cudaGetSymbolAddress(&wol, p_wol);
    cudaGetSymbolAddress(&peh, p_peh); cudaGetSymbolAddress(&pel, p_pel);
    cudaGetSymbolAddress(&wrh, p_wrh); cudaGetSymbolAddress(&wrl, p_wrl);

    auto pk = [&](const float* src, void* dh, void* dl, size_t n, size_t eoff) {
        int n4 = (int)(n / 4);
        pack_hl<<<(n4 + 255) / 256, 256>>>(
            (const float4*)src,
            (u64*)((char*)dh + eoff * 2), (u64*)((char*)dl + eoff * 2), n4);
    };
    pk(x,    xh,  xl,  (size_t)BN * DIMX, 0);
    pk(Wq,   w3h, w3l, (size_t)DIMX * HD, 0);
    pk(Wk,   w3h, w3l, (size_t)DIMX * HD, (size_t)DIMX * HD);
    pk(Wv,   w3h, w3l, (size_t)DIMX * HD, (size_t)2 * DIMX * HD);
    pk(Wo,   woh, wol, (size_t)HD * DIMX, 0);
    pk(pe,   peh, pel, (size_t)NPOS * NRPFK, 0);
    pk(Wrel, wrh, wrl, (size_t)NRPFK * HD, 0);

    qkv_tc <<<dim3(4, 24, 3), 256, GEMM_SMEM>>>(rcb, rpb);
    relk_tc<<<dim3(4, 24),    256, GEMM_SMEM>>>();
    attn_kernel<<<dim3(16, 24), 128, ATTN_SMEM>>>();
    out_tc <<<dim3(12, 24),   256, GEMM_SMEM>>>(bo, out);
}